// round 11
// baseline (speedup 1.0000x reference)
#include <cuda_runtime.h>
#include <cuda_fp16.h>
#include <cstdint>

#define D 64
#define MAXN 100000
#define MAXE 1600000
#define SCAN_BLK 1024

// Scratch (device globals — no allocation allowed; zero-initialized at load,
// every kernel sequence restores the zero-invariants it consumes)
__device__ float g_agg[MAXN * D];      // agg result; later reused as t2
__device__ float g_t1[MAXN * D];       // output of first Linear
__device__ float g_stats[256];         // sum1[64], sq1[64], sum2[64], sq2[64]
__device__ uint2 g_xh[MAXN * 16];      // x staged as fp16 (64 halfs/row = 128B)
__device__ int   g_cnt[MAXN + SCAN_BLK];  // degree hist (re-zeroed by k_build)
__device__ int   g_start[MAXN + 1];
__device__ int   g_cursor[MAXN];
__device__ int   g_srcs[MAXE];
__device__ int   g_bsum[SCAN_BLK];
__device__ int   g_bar_count;          // grid barrier (self-resetting count)
__device__ int   g_bar_gen;            // generation (monotonic; equality-tested)

// ---------------------------------------------------------------------------
// Grid barrier for a fully-resident grid (NB <= #SMs). Reusable.
// ---------------------------------------------------------------------------
__device__ __forceinline__ void grid_barrier(int NB) {
    __syncthreads();
    if (threadIdx.x == 0) {
        int gen = *(volatile int*)&g_bar_gen;
        __threadfence();
        if (atomicAdd(&g_bar_count, 1) == NB - 1) {
            g_bar_count = 0;
            __threadfence();
            atomicAdd(&g_bar_gen, 1);
        } else {
            while (*(volatile int*)&g_bar_gen == gen) {}
        }
        __threadfence();
    }
    __syncthreads();
}

__device__ __forceinline__ int block_scan_1024(int v, int* warpsum, int* total) {
    int lane = threadIdx.x & 31, wid = threadIdx.x >> 5;
    int inc = v;
    #pragma unroll
    for (int o = 1; o < 32; o <<= 1) {
        int u = __shfl_up_sync(0xFFFFFFFFu, inc, o);
        if (lane >= o) inc += u;
    }
    if (lane == 31) warpsum[wid] = inc;
    __syncthreads();
    if (wid == 0) {
        int w = warpsum[lane];
        #pragma unroll
        for (int o = 1; o < 32; o <<= 1) {
            int u = __shfl_up_sync(0xFFFFFFFFu, w, o);
            if (lane >= o) w += u;
        }
        warpsum[lane] = w;
    }
    __syncthreads();
    int base = (wid > 0) ? warpsum[wid - 1] : 0;
    *total = warpsum[31];
    return inc + base;
}

// ---------------------------------------------------------------------------
// K_build: ONE resident kernel = fp16 staging + hist + scan + fill.
// Grid: NB blocks x 1024, NB = ceil(N/1024) = 98 <= 148 SMs (resident).
// ---------------------------------------------------------------------------
__global__ __launch_bounds__(SCAN_BLK) void k_build(const float* __restrict__ x,
                                                    const int* __restrict__ ei,
                                                    int N, int E) {
    __shared__ int warpsum[32];
    __shared__ int s_base;
    const int NB = gridDim.x;
    const int gsz = NB * SCAN_BLK;
    const int gt = blockIdx.x * SCAN_BLK + threadIdx.x;

    // --- Phase A: zero stats, stage x -> fp16, degree histogram ---
    if (gt < 256) g_stats[gt] = 0.f;
    if (gt == 0) g_start[N] = E;
    int n4 = N * 16;
    for (int i = gt; i < n4; i += gsz) {
        float4 v = ((const float4*)x)[i];
        __half2 h0 = __floats2half2_rn(v.x, v.y);
        __half2 h1 = __floats2half2_rn(v.z, v.w);
        uint2 u;
        u.x = *(unsigned*)&h0;
        u.y = *(unsigned*)&h1;
        g_xh[i] = u;
    }
    for (int e = gt; e < E; e += gsz)
        atomicAdd(&g_cnt[ei[E + e]], 1);

    grid_barrier(NB);

    // --- Phase B: exclusive scan of degrees -> g_start / g_cursor ---
    int v = (gt < N) ? g_cnt[gt] : 0;
    if (gt < N) g_cnt[gt] = 0;                 // restore zero-invariant
    int total;
    int incl = block_scan_1024(v, warpsum, &total);
    if (threadIdx.x == 0) g_bsum[blockIdx.x] = total;

    grid_barrier(NB);

    if (threadIdx.x < 32) {
        int base = 0;
        for (int j = threadIdx.x; j < (int)blockIdx.x; j += 32) base += g_bsum[j];
        #pragma unroll
        for (int o = 16; o >= 1; o >>= 1) base += __shfl_down_sync(0xFFFFFFFFu, base, o);
        if (threadIdx.x == 0) s_base = base;
    }
    __syncthreads();
    if (gt < N) {
        int st = s_base + incl - v;
        g_start[gt] = st;
        g_cursor[gt] = st;
    }

    grid_barrier(NB);

    // --- Phase C: fill srcs grouped by dst ---
    for (int e = gt; e < E; e += gsz) {
        int src = ei[e];
        int dst = ei[E + e];
        int pos = atomicAdd(&g_cursor[dst], 1);
        g_srcs[pos] = src;
    }
}

// ---------------------------------------------------------------------------
// K_agg: (1+eps)*x[i](fp32) + sum of fp16 neighbor rows.
// 8 threads per node, uint4 (16B) gathers. (R9 version — best measured.)
// ---------------------------------------------------------------------------
__global__ __launch_bounds__(256) void k_agg(const float* __restrict__ x,
                                             const float* __restrict__ epsp,
                                             float* __restrict__ agg, int N) {
    int tid = threadIdx.x;
    int i = blockIdx.x * 32 + (tid >> 3);
    int q = tid & 7;
    if (i >= N) return;
    float s = 1.0f + epsp[0];
    float4 x0 = ((const float4*)x)[(size_t)i * 16 + q * 2];
    float4 x1 = ((const float4*)x)[(size_t)i * 16 + q * 2 + 1];
    float4 acc0 = make_float4(x0.x * s, x0.y * s, x0.z * s, x0.w * s);
    float4 acc1 = make_float4(x1.x * s, x1.y * s, x1.z * s, x1.w * s);
    int j = g_start[i];
    int je = g_start[i + 1];
    const uint4* xh4 = (const uint4*)g_xh;
    for (; j < je; j++) {
        int src = g_srcs[j];
        uint4 u = xh4[(size_t)src * 8 + q];
        float2 f0 = __half22float2(*(__half2*)&u.x);
        float2 f1 = __half22float2(*(__half2*)&u.y);
        float2 f2 = __half22float2(*(__half2*)&u.z);
        float2 f3 = __half22float2(*(__half2*)&u.w);
        acc0.x += f0.x; acc0.y += f0.y; acc0.z += f1.x; acc0.w += f1.y;
        acc1.x += f2.x; acc1.y += f2.y; acc1.z += f3.x; acc1.w += f3.y;
    }
    ((float4*)agg)[(size_t)i * 16 + q * 2] = acc0;
    ((float4*)agg)[(size_t)i * 16 + q * 2 + 1] = acc1;
}

// ---------------------------------------------------------------------------
// fp16 HMMA GEMM (m16n8k16, fp32 accum) + fused BN stats. (verified)
// ---------------------------------------------------------------------------
#define MMA_F16(c, a0, a1, a2, a3, b0, b1)                                    \
    asm volatile(                                                             \
        "mma.sync.aligned.m16n8k16.row.col.f32.f16.f16.f32 "                  \
        "{%0,%1,%2,%3}, {%4,%5,%6,%7}, {%8,%9}, {%0,%1,%2,%3};"               \
        : "+f"(c[0]), "+f"(c[1]), "+f"(c[2]), "+f"(c[3])                      \
        : "r"(a0), "r"(a1), "r"(a2), "r"(a3), "r"(b0), "r"(b1))

__global__ __launch_bounds__(256) void k_gemm_hmma(
    const float* __restrict__ in, const float* __restrict__ W,
    const float* __restrict__ b, float* __restrict__ out,
    float* __restrict__ statsOut,
    const float* __restrict__ statsIn,
    const float* __restrict__ gamma, const float* __restrict__ beta,
    int N, int applyBNin)
{
    __shared__ unsigned Xs[64 * 68];
    __shared__ unsigned Wsm[32 * 72];
    __shared__ float Bs[64], SC[64], SH[64];
    __shared__ float redS[8][32], redQ[8][32];

    const int tid = threadIdx.x;
    const int row0 = blockIdx.x * 64;

    if (tid < 64) {
        Bs[tid] = b[tid];
        if (applyBNin) {
            float invN = 1.0f / (float)N;
            float mean = statsIn[tid] * invN;
            float var  = statsIn[64 + tid] * invN - mean * mean;
            float sc = gamma[tid] * rsqrtf(var + 1e-5f);
            SC[tid] = sc;
            SH[tid] = beta[tid] - mean * sc;
        }
    }
    __syncthreads();

    #pragma unroll
    for (int it = 0; it < 8; it++) {
        int idx = tid + it * 256;
        int k2 = idx >> 6, n = idx & 63;
        float w0 = W[(2 * k2) * 64 + n];
        float w1 = W[(2 * k2 + 1) * 64 + n];
        __half2 h = __floats2half2_rn(w0, w1);
        Wsm[k2 * 72 + n] = *(unsigned*)&h;
    }
    #pragma unroll
    for (int it = 0; it < 8; it++) {
        int idx = tid + it * 256;
        int row = idx >> 5, k2 = idx & 31;
        int gr = row0 + row;
        float2 v = make_float2(0.f, 0.f);
        if (gr < N) v = ((const float2*)in)[(size_t)gr * 32 + k2];
        if (applyBNin) {
            int c = k2 * 2;
            v.x = fmaxf(fmaf(v.x, SC[c], SH[c]), 0.f);
            v.y = fmaxf(fmaf(v.y, SC[c + 1], SH[c + 1]), 0.f);
        }
        __half2 h = __floats2half2_rn(v.x, v.y);
        Xs[row * 68 + k2] = *(unsigned*)&h;
    }
    __syncthreads();

    const int w = tid >> 5, lane = tid & 31;
    const int ms = w & 3, nh = w >> 2;
    const int g = lane >> 2, t4 = lane & 3;
    const int mbase = ms * 16;
    const int nbase = nh * 32;

    float c_[4][4];
    #pragma unroll
    for (int nt = 0; nt < 4; nt++) {
        int col0 = nbase + nt * 8 + 2 * t4;
        c_[nt][0] = Bs[col0]; c_[nt][1] = Bs[col0 + 1];
        c_[nt][2] = Bs[col0]; c_[nt][3] = Bs[col0 + 1];
    }

    #pragma unroll
    for (int kk = 0; kk < 4; kk++) {
        int kb = kk * 8;
        unsigned A0 = Xs[(mbase + g) * 68 + kb + t4];
        unsigned A1 = Xs[(mbase + g + 8) * 68 + kb + t4];
        unsigned A2 = Xs[(mbase + g) * 68 + kb + t4 + 4];
        unsigned A3 = Xs[(mbase + g + 8) * 68 + kb + t4 + 4];
        #pragma unroll
        for (int nt = 0; nt < 4; nt++) {
            int n = nbase + nt * 8 + g;
            unsigned B0 = Wsm[(kb + t4) * 72 + n];
            unsigned B1 = Wsm[(kb + t4 + 4) * 72 + n];
            MMA_F16(c_[nt], A0, A1, A2, A3, B0, B1);
        }
    }

    int rg0 = row0 + mbase + g;
    int rg8 = rg0 + 8;
    #pragma unroll
    for (int nt = 0; nt < 4; nt++) {
        int col0 = nbase + nt * 8 + 2 * t4;
        float s0 = 0.f, s1 = 0.f, q0 = 0.f, q1 = 0.f;
        if (rg0 < N) {
            *(float2*)&out[(size_t)rg0 * 64 + col0] = make_float2(c_[nt][0], c_[nt][1]);
            s0 += c_[nt][0]; s1 += c_[nt][1];
            q0 += c_[nt][0] * c_[nt][0]; q1 += c_[nt][1] * c_[nt][1];
        }
        if (rg8 < N) {
            *(float2*)&out[(size_t)rg8 * 64 + col0] = make_float2(c_[nt][2], c_[nt][3]);
            s0 += c_[nt][2]; s1 += c_[nt][3];
            q0 += c_[nt][2] * c_[nt][2]; q1 += c_[nt][3] * c_[nt][3];
        }
        #pragma unroll
        for (int o = 16; o >= 4; o >>= 1) {
            s0 += __shfl_down_sync(0xFFFFFFFFu, s0, o);
            s1 += __shfl_down_sync(0xFFFFFFFFu, s1, o);
            q0 += __shfl_down_sync(0xFFFFFFFFu, q0, o);
            q1 += __shfl_down_sync(0xFFFFFFFFu, q1, o);
        }
        if (lane < 4) {
            redS[w][nt * 8 + 2 * t4] = s0;
            redS[w][nt * 8 + 2 * t4 + 1] = s1;
            redQ[w][nt * 8 + 2 * t4] = q0;
            redQ[w][nt * 8 + 2 * t4 + 1] = q1;
        }
    }
    __syncthreads();
    if (tid < 64) {
        int hh = tid >> 5, lc = tid & 31;
        float s = redS[hh * 4 + 0][lc] + redS[hh * 4 + 1][lc]
                + redS[hh * 4 + 2][lc] + redS[hh * 4 + 3][lc];
        float q = redQ[hh * 4 + 0][lc] + redQ[hh * 4 + 1][lc]
                + redQ[hh * 4 + 2][lc] + redQ[hh * 4 + 3][lc];
        atomicAdd(&statsOut[tid], s);
        atomicAdd(&statsOut[64 + tid], q);
    }
}

// ---------------------------------------------------------------------------
// K_final: out = x + relu(BN(t2))
// ---------------------------------------------------------------------------
__global__ __launch_bounds__(256) void k_final(const float* __restrict__ x,
                                               const float* __restrict__ t2,
                                               const float* __restrict__ statsIn,
                                               const float* __restrict__ gamma,
                                               const float* __restrict__ beta,
                                               float* __restrict__ out, int N) {
    __shared__ float SC[64];
    __shared__ float SH[64];
    int tid = threadIdx.x;
    if (tid < 64) {
        float invN = 1.0f / (float)N;
        float mean = statsIn[tid] * invN;
        float var  = statsIn[64 + tid] * invN - mean * mean;
        float sc = gamma[tid] * rsqrtf(var + 1e-5f);
        SC[tid] = sc;
        SH[tid] = beta[tid] - mean * sc;
    }
    __syncthreads();
    int n4 = N * 16;
    for (int i = blockIdx.x * 256 + tid; i < n4; i += gridDim.x * 256) {
        int c = (i & 15) * 4;
        float4 v = ((const float4*)t2)[i];
        float4 xv = ((const float4*)x)[i];
        float4 o;
        o.x = xv.x + fmaxf(fmaf(v.x, SC[c + 0], SH[c + 0]), 0.f);
        o.y = xv.y + fmaxf(fmaf(v.y, SC[c + 1], SH[c + 1]), 0.f);
        o.z = xv.z + fmaxf(fmaf(v.z, SC[c + 2], SH[c + 2]), 0.f);
        o.w = xv.w + fmaxf(fmaf(v.w, SC[c + 3], SH[c + 3]), 0.f);
        ((float4*)out)[i] = o;
    }
}

// ---------------------------------------------------------------------------
extern "C" void kernel_launch(void* const* d_in, const int* in_sizes, int n_in,
                              void* d_out, int out_size) {
    const float* x    = (const float*)d_in[0];
    const int*   ei   = (const int*)d_in[1];
    const float* eps  = (const float*)d_in[2];
    const float* W1   = (const float*)d_in[3];
    const float* b1   = (const float*)d_in[4];
    const float* g1   = (const float*)d_in[5];
    const float* beta1= (const float*)d_in[6];
    const float* W2   = (const float*)d_in[7];
    const float* b2   = (const float*)d_in[8];
    const float* gh   = (const float*)d_in[9];
    const float* betah= (const float*)d_in[10];
    float* out = (float*)d_out;

    int N = in_sizes[0] / D;
    int E = in_sizes[1] / 2;
    if (N > MAXN) N = MAXN;
    if (E > MAXE) E = MAXE;

    float* agg;   cudaGetSymbolAddress((void**)&agg, g_agg);
    float* t1;    cudaGetSymbolAddress((void**)&t1, g_t1);
    float* stats; cudaGetSymbolAddress((void**)&stats, g_stats);

    int NB = (N + SCAN_BLK - 1) / SCAN_BLK;   // 98 <= 148 SMs: fully resident

    k_build<<<NB, SCAN_BLK>>>(x, ei, N, E);
    k_agg<<<(N + 31) / 32, 256>>>(x, eps, agg, N);

    int gemmBlocks = (N + 63) / 64;
    k_gemm_hmma<<<gemmBlocks, 256>>>(agg, W1, b1, t1, stats,
                                     nullptr, nullptr, nullptr, N, 0);
    k_gemm_hmma<<<gemmBlocks, 256>>>(t1, W2, b2, agg, stats + 128,
                                     stats, g1, beta1, N, 1);

    k_final<<<(N * 16 + 255) / 256, 256>>>(x, agg, stats + 128, gh, betah, out, N);
}

// round 12
// speedup vs baseline: 1.1708x; 1.1708x over previous
#include <cuda_runtime.h>
#include <cuda_fp16.h>
#include <cstdint>

#define D 64
#define MAXN 100000
#define MAXE 1600000
#define SCAN_BLK 1024

// Scratch (device globals — no allocation allowed)
__device__ float    g_agg[MAXN * D];     // gemm2 output (t2)
__device__ float    g_t1[MAXN * D];      // gemm1 output
__device__ float    g_stats[256];        // sum1, sq1, sum2, sq2
__device__ uint2    g_xh[MAXN * 16];     // x staged fp16 (gather source)
__device__ uint4    g_aggh[MAXN * 8];    // agg result, packed fp16 rows
__device__ unsigned g_w1h[32 * 64];      // W1 fp16 [k2][n] half2(k-pair)
__device__ unsigned g_w2h[32 * 64];      // W2 fp16 [k2][n]
__device__ int      g_cnt[MAXN + SCAN_BLK];
__device__ int      g_start[MAXN + 1];
__device__ int      g_cursor[MAXN];
__device__ int      g_srcs[MAXE];
__device__ int      g_bsum[SCAN_BLK];
__device__ int      g_ctr, g_ctr2;

// ---------------------------------------------------------------------------
// K_prep: stage x as fp16 + degree hist + zero stats + W1/W2 -> fp16 [k2][n]
// ---------------------------------------------------------------------------
__global__ __launch_bounds__(256) void k_prep(const float* __restrict__ x,
                                              const int* __restrict__ ei,
                                              const float* __restrict__ W1,
                                              const float* __restrict__ W2,
                                              int N, int E) {
    int i = blockIdx.x * 256 + threadIdx.x;
    if (i < 256) g_stats[i] = 0.f;
    if (i == 0) g_start[N] = E;
    if (i < 2048) {
        int k2 = i >> 6, n = i & 63;
        __half2 h = __floats2half2_rn(W1[(2 * k2) * 64 + n], W1[(2 * k2 + 1) * 64 + n]);
        g_w1h[k2 * 64 + n] = *(unsigned*)&h;
    } else if (i < 4096) {
        int j = i - 2048;
        int k2 = j >> 6, n = j & 63;
        __half2 h = __floats2half2_rn(W2[(2 * k2) * 64 + n], W2[(2 * k2 + 1) * 64 + n]);
        g_w2h[k2 * 64 + n] = *(unsigned*)&h;
    }
    if (i < E) atomicAdd(&g_cnt[ei[E + i]], 1);
    int n4 = N * 16;
    if (i >= n4) return;
    float4 v = ((const float4*)x)[i];
    __half2 h0 = __floats2half2_rn(v.x, v.y);
    __half2 h1 = __floats2half2_rn(v.z, v.w);
    uint2 u;
    u.x = *(unsigned*)&h0;
    u.y = *(unsigned*)&h1;
    g_xh[i] = u;
}

__device__ __forceinline__ int block_scan_1024(int v, int* warpsum, int* total) {
    int lane = threadIdx.x & 31, wid = threadIdx.x >> 5;
    int inc = v;
    #pragma unroll
    for (int o = 1; o < 32; o <<= 1) {
        int u = __shfl_up_sync(0xFFFFFFFFu, inc, o);
        if (lane >= o) inc += u;
    }
    if (lane == 31) warpsum[wid] = inc;
    __syncthreads();
    if (wid == 0) {
        int w = warpsum[lane];
        #pragma unroll
        for (int o = 1; o < 32; o <<= 1) {
            int u = __shfl_up_sync(0xFFFFFFFFu, w, o);
            if (lane >= o) w += u;
        }
        warpsum[lane] = w;
    }
    __syncthreads();
    int base = (wid > 0) ? warpsum[wid - 1] : 0;
    *total = warpsum[31];
    return inc + base;
}

// K_scan: single-kernel exclusive scan (R9 version — resident grid)
__global__ __launch_bounds__(SCAN_BLK) void k_scan(int N) {
    __shared__ int warpsum[32];
    __shared__ int s_base;
    int gi = blockIdx.x * SCAN_BLK + threadIdx.x;
    int v = (gi < N) ? g_cnt[gi] : 0;
    if (gi < N) g_cnt[gi] = 0;
    int total;
    int incl = block_scan_1024(v, warpsum, &total);

    if (threadIdx.x == 0) {
        g_bsum[blockIdx.x] = total;
        __threadfence();
        atomicAdd(&g_ctr, 1);
        while (atomicAdd(&g_ctr, 0) < (int)gridDim.x) {}
        __threadfence();
    }
    __syncthreads();

    if (threadIdx.x < 32) {
        int base = 0;
        for (int j = threadIdx.x; j < (int)blockIdx.x; j += 32) base += g_bsum[j];
        #pragma unroll
        for (int o = 16; o >= 1; o >>= 1) base += __shfl_down_sync(0xFFFFFFFFu, base, o);
        if (threadIdx.x == 0) s_base = base;
    }
    __syncthreads();

    if (gi < N) {
        int st = s_base + incl - v;
        g_start[gi] = st;
        g_cursor[gi] = st;
    }
    if (threadIdx.x == 0) {
        int done = atomicAdd(&g_ctr2, 1);
        if (done == (int)gridDim.x - 1) { g_ctr = 0; g_ctr2 = 0; }
    }
}

__global__ __launch_bounds__(256) void k_fill(const int* __restrict__ ei, int E) {
    int e = blockIdx.x * 256 + threadIdx.x;
    if (e >= E) return;
    int src = ei[e];
    int dst = ei[E + e];
    int pos = atomicAdd(&g_cursor[dst], 1);
    g_srcs[pos] = src;
}

// ---------------------------------------------------------------------------
// K_agg: (1+eps)*x[i](fp32) + fp16 neighbor sum, OUTPUT packed fp16 rows.
// (Same arithmetic as R9 up to the final fp32->fp16 store, which gemm1 did
//  anyway during staging — identical rounding, half the write traffic.)
// ---------------------------------------------------------------------------
__global__ __launch_bounds__(256) void k_agg(const float* __restrict__ x,
                                             const float* __restrict__ epsp,
                                             int N) {
    int tid = threadIdx.x;
    int i = blockIdx.x * 32 + (tid >> 3);
    int q = tid & 7;
    if (i >= N) return;
    float s = 1.0f + epsp[0];
    float4 x0 = ((const float4*)x)[(size_t)i * 16 + q * 2];
    float4 x1 = ((const float4*)x)[(size_t)i * 16 + q * 2 + 1];
    float4 acc0 = make_float4(x0.x * s, x0.y * s, x0.z * s, x0.w * s);
    float4 acc1 = make_float4(x1.x * s, x1.y * s, x1.z * s, x1.w * s);
    int j = g_start[i];
    int je = g_start[i + 1];
    const uint4* xh4 = (const uint4*)g_xh;
    for (; j < je; j++) {
        int src = g_srcs[j];
        uint4 u = xh4[(size_t)src * 8 + q];
        float2 f0 = __half22float2(*(__half2*)&u.x);
        float2 f1 = __half22float2(*(__half2*)&u.y);
        float2 f2 = __half22float2(*(__half2*)&u.z);
        float2 f3 = __half22float2(*(__half2*)&u.w);
        acc0.x += f0.x; acc0.y += f0.y; acc0.z += f1.x; acc0.w += f1.y;
        acc1.x += f2.x; acc1.y += f2.y; acc1.z += f3.x; acc1.w += f3.y;
    }
    __half2 h0 = __floats2half2_rn(acc0.x, acc0.y);
    __half2 h1 = __floats2half2_rn(acc0.z, acc0.w);
    __half2 h2 = __floats2half2_rn(acc1.x, acc1.y);
    __half2 h3 = __floats2half2_rn(acc1.z, acc1.w);
    uint4 o;
    o.x = *(unsigned*)&h0; o.y = *(unsigned*)&h1;
    o.z = *(unsigned*)&h2; o.w = *(unsigned*)&h3;
    g_aggh[(size_t)i * 8 + q] = o;
}

// ---------------------------------------------------------------------------
// fp16 HMMA GEMM + fused BN stats. W comes PRE-CONVERTED fp16 [k2][n].
// X path A (inH != null): packed fp16 rows, pure uint4 copy staging.
// X path B (inF): fp32 + optional BN+ReLU, convert during staging.
// ---------------------------------------------------------------------------
#define MMA_F16(c, a0, a1, a2, a3, b0, b1)                                    \
    asm volatile(                                                             \
        "mma.sync.aligned.m16n8k16.row.col.f32.f16.f16.f32 "                  \
        "{%0,%1,%2,%3}, {%4,%5,%6,%7}, {%8,%9}, {%0,%1,%2,%3};"               \
        : "+f"(c[0]), "+f"(c[1]), "+f"(c[2]), "+f"(c[3])                      \
        : "r"(a0), "r"(a1), "r"(a2), "r"(a3), "r"(b0), "r"(b1))

__global__ __launch_bounds__(256) void k_gemm_hmma(
    const uint4* __restrict__ inH, const float* __restrict__ inF,
    const unsigned* __restrict__ Wh,
    const float* __restrict__ b, float* __restrict__ out,
    float* __restrict__ statsOut,
    const float* __restrict__ statsIn,
    const float* __restrict__ gamma, const float* __restrict__ beta,
    int N, int applyBNin)
{
    __shared__ unsigned Xs[64 * 68];
    __shared__ unsigned Wsm[32 * 72];
    __shared__ float Bs[64], SC[64], SH[64];
    __shared__ float redS[8][32], redQ[8][32];

    const int tid = threadIdx.x;
    const int row0 = blockIdx.x * 64;

    if (tid < 64) {
        Bs[tid] = b[tid];
        if (applyBNin) {
            float invN = 1.0f / (float)N;
            float mean = statsIn[tid] * invN;
            float var  = statsIn[64 + tid] * invN - mean * mean;
            float sc = gamma[tid] * rsqrtf(var + 1e-5f);
            SC[tid] = sc;
            SH[tid] = beta[tid] - mean * sc;
        }
    }
    __syncthreads();

    // Stage W: uint4 copy of pre-converted fp16 (512 LDG.128 + STS.128)
    #pragma unroll
    for (int it = 0; it < 2; it++) {
        int idx = tid + it * 256;            // 0..511
        int k2 = idx >> 4, nq = idx & 15;
        uint4 u = ((const uint4*)Wh)[k2 * 16 + nq];
        *(uint4*)&Wsm[k2 * 72 + nq * 4] = u;
    }
    // Stage X
    if (inH) {
        #pragma unroll
        for (int it = 0; it < 2; it++) {
            int idx = tid + it * 256;        // 0..511
            int row = idx >> 3, w4 = idx & 7;
            int gr = row0 + row;
            uint4 u = make_uint4(0u, 0u, 0u, 0u);
            if (gr < N) u = inH[(size_t)gr * 8 + w4];
            *(uint4*)&Xs[row * 68 + w4 * 4] = u;
        }
    } else {
        #pragma unroll
        for (int it = 0; it < 8; it++) {
            int idx = tid + it * 256;
            int row = idx >> 5, k2 = idx & 31;
            int gr = row0 + row;
            float2 v = make_float2(0.f, 0.f);
            if (gr < N) v = ((const float2*)inF)[(size_t)gr * 32 + k2];
            if (applyBNin) {
                int c = k2 * 2;
                v.x = fmaxf(fmaf(v.x, SC[c], SH[c]), 0.f);
                v.y = fmaxf(fmaf(v.y, SC[c + 1], SH[c + 1]), 0.f);
            }
            __half2 h = __floats2half2_rn(v.x, v.y);
            Xs[row * 68 + k2] = *(unsigned*)&h;
        }
    }
    __syncthreads();

    const int w = tid >> 5, lane = tid & 31;
    const int ms = w & 3, nh = w >> 2;
    const int g = lane >> 2, t4 = lane & 3;
    const int mbase = ms * 16;
    const int nbase = nh * 32;

    float c_[4][4];
    #pragma unroll
    for (int nt = 0; nt < 4; nt++) {
        int col0 = nbase + nt * 8 + 2 * t4;
        c_[nt][0] = Bs[col0]; c_[nt][1] = Bs[col0 + 1];
        c_[nt][2] = Bs[col0]; c_[nt][3] = Bs[col0 + 1];
    }

    #pragma unroll
    for (int kk = 0; kk < 4; kk++) {
        int kb = kk * 8;
        unsigned A0 = Xs[(mbase + g) * 68 + kb + t4];
        unsigned A1 = Xs[(mbase + g + 8) * 68 + kb + t4];
        unsigned A2 = Xs[(mbase + g) * 68 + kb + t4 + 4];
        unsigned A3 = Xs[(mbase + g + 8) * 68 + kb + t4 + 4];
        #pragma unroll
        for (int nt = 0; nt < 4; nt++) {
            int n = nbase + nt * 8 + g;
            unsigned B0 = Wsm[(kb + t4) * 72 + n];
            unsigned B1 = Wsm[(kb + t4 + 4) * 72 + n];
            MMA_F16(c_[nt], A0, A1, A2, A3, B0, B1);
        }
    }

    int rg0 = row0 + mbase + g;
    int rg8 = rg0 + 8;
    #pragma unroll
    for (int nt = 0; nt < 4; nt++) {
        int col0 = nbase + nt * 8 + 2 * t4;
        float s0 = 0.f, s1 = 0.f, q0 = 0.f, q1 = 0.f;
        if (rg0 < N) {
            *(float2*)&out[(size_t)rg0 * 64 + col0] = make_float2(c_[nt][0], c_[nt][1]);
            s0 += c_[nt][0]; s1 += c_[nt][1];
            q0 += c_[nt][0] * c_[nt][0]; q1 += c_[nt][1] * c_[nt][1];
        }
        if (rg8 < N) {
            *(float2*)&out[(size_t)rg8 * 64 + col0] = make_float2(c_[nt][2], c_[nt][3]);
            s0 += c_[nt][2]; s1 += c_[nt][3];
            q0 += c_[nt][2] * c_[nt][2]; q1 += c_[nt][3] * c_[nt][3];
        }
        #pragma unroll
        for (int o = 16; o >= 4; o >>= 1) {
            s0 += __shfl_down_sync(0xFFFFFFFFu, s0, o);
            s1 += __shfl_down_sync(0xFFFFFFFFu, s1, o);
            q0 += __shfl_down_sync(0xFFFFFFFFu, q0, o);
            q1 += __shfl_down_sync(0xFFFFFFFFu, q1, o);
        }
        if (lane < 4) {
            redS[w][nt * 8 + 2 * t4] = s0;
            redS[w][nt * 8 + 2 * t4 + 1] = s1;
            redQ[w][nt * 8 + 2 * t4] = q0;
            redQ[w][nt * 8 + 2 * t4 + 1] = q1;
        }
    }
    __syncthreads();
    if (tid < 64) {
        int hh = tid >> 5, lc = tid & 31;
        float s = redS[hh * 4 + 0][lc] + redS[hh * 4 + 1][lc]
                + redS[hh * 4 + 2][lc] + redS[hh * 4 + 3][lc];
        float q = redQ[hh * 4 + 0][lc] + redQ[hh * 4 + 1][lc]
                + redQ[hh * 4 + 2][lc] + redQ[hh * 4 + 3][lc];
        atomicAdd(&statsOut[tid], s);
        atomicAdd(&statsOut[64 + tid], q);
    }
}

// ---------------------------------------------------------------------------
// K_final: out = x + relu(BN(t2))
// ---------------------------------------------------------------------------
__global__ __launch_bounds__(256) void k_final(const float* __restrict__ x,
                                               const float* __restrict__ t2,
                                               const float* __restrict__ statsIn,
                                               const float* __restrict__ gamma,
                                               const float* __restrict__ beta,
                                               float* __restrict__ out, int N) {
    __shared__ float SC[64];
    __shared__ float SH[64];
    int tid = threadIdx.x;
    if (tid < 64) {
        float invN = 1.0f / (float)N;
        float mean = statsIn[tid] * invN;
        float var  = statsIn[64 + tid] * invN - mean * mean;
        float sc = gamma[tid] * rsqrtf(var + 1e-5f);
        SC[tid] = sc;
        SH[tid] = beta[tid] - mean * sc;
    }
    __syncthreads();
    int n4 = N * 16;
    for (int i = blockIdx.x * 256 + tid; i < n4; i += gridDim.x * 256) {
        int c = (i & 15) * 4;
        float4 v = ((const float4*)t2)[i];
        float4 xv = ((const float4*)x)[i];
        float4 o;
        o.x = xv.x + fmaxf(fmaf(v.x, SC[c + 0], SH[c + 0]), 0.f);
        o.y = xv.y + fmaxf(fmaf(v.y, SC[c + 1], SH[c + 1]), 0.f);
        o.z = xv.z + fmaxf(fmaf(v.z, SC[c + 2], SH[c + 2]), 0.f);
        o.w = xv.w + fmaxf(fmaf(v.w, SC[c + 3], SH[c + 3]), 0.f);
        ((float4*)out)[i] = o;
    }
}

// ---------------------------------------------------------------------------
extern "C" void kernel_launch(void* const* d_in, const int* in_sizes, int n_in,
                              void* d_out, int out_size) {
    const float* x    = (const float*)d_in[0];
    const int*   ei   = (const int*)d_in[1];
    const float* eps  = (const float*)d_in[2];
    const float* W1   = (const float*)d_in[3];
    const float* b1   = (const float*)d_in[4];
    const float* g1   = (const float*)d_in[5];
    const float* beta1= (const float*)d_in[6];
    const float* W2   = (const float*)d_in[7];
    const float* b2   = (const float*)d_in[8];
    const float* gh   = (const float*)d_in[9];
    const float* betah= (const float*)d_in[10];
    float* out = (float*)d_out;

    int N = in_sizes[0] / D;
    int E = in_sizes[1] / 2;
    if (N > MAXN) N = MAXN;
    if (E > MAXE) E = MAXE;

    float* agg;      cudaGetSymbolAddress((void**)&agg, g_agg);
    float* t1;       cudaGetSymbolAddress((void**)&t1, g_t1);
    float* stats;    cudaGetSymbolAddress((void**)&stats, g_stats);
    uint4* aggh;     cudaGetSymbolAddress((void**)&aggh, g_aggh);
    unsigned* w1h;   cudaGetSymbolAddress((void**)&w1h, g_w1h);
    unsigned* w2h;   cudaGetSymbolAddress((void**)&w2h, g_w2h);

    int prepThreads = (N * 16 > E) ? N * 16 : E;
    int nScanBlocks = (N + SCAN_BLK - 1) / SCAN_BLK;   // 98 <= 148: resident

    k_prep<<<(prepThreads + 255) / 256, 256>>>(x, ei, W1, W2, N, E);
    k_scan<<<nScanBlocks, SCAN_BLK>>>(N);
    k_fill<<<(E + 255) / 256, 256>>>(ei, E);
    k_agg<<<(N + 31) / 32, 256>>>(x, eps, N);

    int gemmBlocks = (N + 63) / 64;
    // gemm1: X = packed fp16 agg, no BN
    k_gemm_hmma<<<gemmBlocks, 256>>>(aggh, nullptr, w1h, b1, t1, stats,
                                     nullptr, nullptr, nullptr, N, 0);
    // gemm2: X = fp32 t1 with BN+ReLU
    k_gemm_hmma<<<gemmBlocks, 256>>>(nullptr, t1, w2h, b2, agg, stats + 128,
                                     stats, g1, beta1, N, 1);

    k_final<<<(N * 16 + 255) / 256, 256>>>(x, agg, stats + 128, gh, betah, out, N);
}

// round 13
// speedup vs baseline: 1.1986x; 1.0237x over previous
#include <cuda_runtime.h>
#include <cuda_fp16.h>
#include <cstdint>

#define D 64
#define MAXN 100000
#define MAXE 1600000
#define SCAN_BLK 1024

// Scratch (device globals — no allocation allowed)
__device__ float    g_agg[MAXN * D];     // gemm2 output (t2)
__device__ float    g_t1[MAXN * D];      // gemm1 output
__device__ float    g_stats[256];        // sum1, sq1, sum2, sq2
__device__ uint2    g_xh[MAXN * 16];     // x staged fp16 (gather source)
__device__ uint4    g_aggh[MAXN * 8];    // agg result, packed fp16 rows
__device__ unsigned g_w1h[32 * 64];      // W1 fp16 [k2][n] half2(k-pair)
__device__ unsigned g_w2h[32 * 64];      // W2 fp16 [k2][n]
__device__ int      g_cnt[MAXN + SCAN_BLK];
__device__ int      g_start[MAXN + 1];
__device__ int      g_cursor[MAXN];
__device__ int      g_srcs[MAXE];
__device__ int      g_bsum[SCAN_BLK];
__device__ int      g_ctr, g_ctr2;

// ---------------------------------------------------------------------------
// K_prep: stage x as fp16 + degree hist + zero stats + W1/W2 -> fp16 [k2][n]
// ---------------------------------------------------------------------------
__global__ __launch_bounds__(256) void k_prep(const float* __restrict__ x,
                                              const int* __restrict__ ei,
                                              const float* __restrict__ W1,
                                              const float* __restrict__ W2,
                                              int N, int E) {
    int i = blockIdx.x * 256 + threadIdx.x;
    if (i < 256) g_stats[i] = 0.f;
    if (i == 0) g_start[N] = E;
    if (i < 2048) {
        int k2 = i >> 6, n = i & 63;
        __half2 h = __floats2half2_rn(W1[(2 * k2) * 64 + n], W1[(2 * k2 + 1) * 64 + n]);
        g_w1h[k2 * 64 + n] = *(unsigned*)&h;
    } else if (i < 4096) {
        int j = i - 2048;
        int k2 = j >> 6, n = j & 63;
        __half2 h = __floats2half2_rn(W2[(2 * k2) * 64 + n], W2[(2 * k2 + 1) * 64 + n]);
        g_w2h[k2 * 64 + n] = *(unsigned*)&h;
    }
    if (i < E) atomicAdd(&g_cnt[ei[E + i]], 1);
    int n4 = N * 16;
    if (i >= n4) return;
    float4 v = ((const float4*)x)[i];
    __half2 h0 = __floats2half2_rn(v.x, v.y);
    __half2 h1 = __floats2half2_rn(v.z, v.w);
    uint2 u;
    u.x = *(unsigned*)&h0;
    u.y = *(unsigned*)&h1;
    g_xh[i] = u;
}

__device__ __forceinline__ int block_scan_1024(int v, int* warpsum, int* total) {
    int lane = threadIdx.x & 31, wid = threadIdx.x >> 5;
    int inc = v;
    #pragma unroll
    for (int o = 1; o < 32; o <<= 1) {
        int u = __shfl_up_sync(0xFFFFFFFFu, inc, o);
        if (lane >= o) inc += u;
    }
    if (lane == 31) warpsum[wid] = inc;
    __syncthreads();
    if (wid == 0) {
        int w = warpsum[lane];
        #pragma unroll
        for (int o = 1; o < 32; o <<= 1) {
            int u = __shfl_up_sync(0xFFFFFFFFu, w, o);
            if (lane >= o) w += u;
        }
        warpsum[lane] = w;
    }
    __syncthreads();
    int base = (wid > 0) ? warpsum[wid - 1] : 0;
    *total = warpsum[31];
    return inc + base;
}

// K_scan: single-kernel exclusive scan (resident grid, verified)
__global__ __launch_bounds__(SCAN_BLK) void k_scan(int N) {
    __shared__ int warpsum[32];
    __shared__ int s_base;
    int gi = blockIdx.x * SCAN_BLK + threadIdx.x;
    int v = (gi < N) ? g_cnt[gi] : 0;
    if (gi < N) g_cnt[gi] = 0;
    int total;
    int incl = block_scan_1024(v, warpsum, &total);

    if (threadIdx.x == 0) {
        g_bsum[blockIdx.x] = total;
        __threadfence();
        atomicAdd(&g_ctr, 1);
        while (atomicAdd(&g_ctr, 0) < (int)gridDim.x) {}
        __threadfence();
    }
    __syncthreads();

    if (threadIdx.x < 32) {
        int base = 0;
        for (int j = threadIdx.x; j < (int)blockIdx.x; j += 32) base += g_bsum[j];
        #pragma unroll
        for (int o = 16; o >= 1; o >>= 1) base += __shfl_down_sync(0xFFFFFFFFu, base, o);
        if (threadIdx.x == 0) s_base = base;
    }
    __syncthreads();

    if (gi < N) {
        int st = s_base + incl - v;
        g_start[gi] = st;
        g_cursor[gi] = st;
    }
    if (threadIdx.x == 0) {
        int done = atomicAdd(&g_ctr2, 1);
        if (done == (int)gridDim.x - 1) { g_ctr = 0; g_ctr2 = 0; }
    }
}

__global__ __launch_bounds__(256) void k_fill(const int* __restrict__ ei, int E) {
    int e = blockIdx.x * 256 + threadIdx.x;
    if (e >= E) return;
    int src = ei[e];
    int dst = ei[E + e];
    int pos = atomicAdd(&g_cursor[dst], 1);
    g_srcs[pos] = src;
}

// ---------------------------------------------------------------------------
// K_agg: (1+eps)*x[i](fp32) + fp16 neighbor sum, output packed fp16 rows.
// 8 threads/node, uint4 gathers. Pairwise HADD2 tree-add: per 2 edges,
// 4 HADD2 + 8 CVT + 8 FADD (was 16 CVT + 16 FADD). Independent loads,
// 1-deep fp16 tree, unchanged fp32 accumulator chain.
// ---------------------------------------------------------------------------
__global__ __launch_bounds__(256) void k_agg(const float* __restrict__ x,
                                             const float* __restrict__ epsp,
                                             int N) {
    int tid = threadIdx.x;
    int i = blockIdx.x * 32 + (tid >> 3);
    int q = tid & 7;
    if (i >= N) return;
    float s = 1.0f + epsp[0];
    float4 x0 = ((const float4*)x)[(size_t)i * 16 + q * 2];
    float4 x1 = ((const float4*)x)[(size_t)i * 16 + q * 2 + 1];
    float4 acc0 = make_float4(x0.x * s, x0.y * s, x0.z * s, x0.w * s);
    float4 acc1 = make_float4(x1.x * s, x1.y * s, x1.z * s, x1.w * s);
    int j = g_start[i];
    int je = g_start[i + 1];
    const uint4* xh4 = (const uint4*)g_xh;
    for (; j + 2 <= je; j += 2) {
        int s0 = g_srcs[j];
        int s1 = g_srcs[j + 1];
        uint4 u0 = xh4[(size_t)s0 * 8 + q];
        uint4 u1 = xh4[(size_t)s1 * 8 + q];
        __half2 p0 = __hadd2(*(__half2*)&u0.x, *(__half2*)&u1.x);
        __half2 p1 = __hadd2(*(__half2*)&u0.y, *(__half2*)&u1.y);
        __half2 p2 = __hadd2(*(__half2*)&u0.z, *(__half2*)&u1.z);
        __half2 p3 = __hadd2(*(__half2*)&u0.w, *(__half2*)&u1.w);
        float2 f0 = __half22float2(p0);
        float2 f1 = __half22float2(p1);
        float2 f2 = __half22float2(p2);
        float2 f3 = __half22float2(p3);
        acc0.x += f0.x; acc0.y += f0.y; acc0.z += f1.x; acc0.w += f1.y;
        acc1.x += f2.x; acc1.y += f2.y; acc1.z += f3.x; acc1.w += f3.y;
    }
    if (j < je) {
        uint4 u = xh4[(size_t)g_srcs[j] * 8 + q];
        float2 f0 = __half22float2(*(__half2*)&u.x);
        float2 f1 = __half22float2(*(__half2*)&u.y);
        float2 f2 = __half22float2(*(__half2*)&u.z);
        float2 f3 = __half22float2(*(__half2*)&u.w);
        acc0.x += f0.x; acc0.y += f0.y; acc0.z += f1.x; acc0.w += f1.y;
        acc1.x += f2.x; acc1.y += f2.y; acc1.z += f3.x; acc1.w += f3.y;
    }
    __half2 h0 = __floats2half2_rn(acc0.x, acc0.y);
    __half2 h1 = __floats2half2_rn(acc0.z, acc0.w);
    __half2 h2 = __floats2half2_rn(acc1.x, acc1.y);
    __half2 h3 = __floats2half2_rn(acc1.z, acc1.w);
    uint4 o;
    o.x = *(unsigned*)&h0; o.y = *(unsigned*)&h1;
    o.z = *(unsigned*)&h2; o.w = *(unsigned*)&h3;
    g_aggh[(size_t)i * 8 + q] = o;
}

// ---------------------------------------------------------------------------
// fp16 HMMA GEMM + fused BN stats (R12 verified version)
// ---------------------------------------------------------------------------
#define MMA_F16(c, a0, a1, a2, a3, b0, b1)                                    \
    asm volatile(                                                             \
        "mma.sync.aligned.m16n8k16.row.col.f32.f16.f16.f32 "                  \
        "{%0,%1,%2,%3}, {%4,%5,%6,%7}, {%8,%9}, {%0,%1,%2,%3};"               \
        : "+f"(c[0]), "+f"(c[1]), "+f"(c[2]), "+f"(c[3])                      \
        : "r"(a0), "r"(a1), "r"(a2), "r"(a3), "r"(b0), "r"(b1))

__global__ __launch_bounds__(256) void k_gemm_hmma(
    const uint4* __restrict__ inH, const float* __restrict__ inF,
    const unsigned* __restrict__ Wh,
    const float* __restrict__ b, float* __restrict__ out,
    float* __restrict__ statsOut,
    const float* __restrict__ statsIn,
    const float* __restrict__ gamma, const float* __restrict__ beta,
    int N, int applyBNin)
{
    __shared__ unsigned Xs[64 * 68];
    __shared__ unsigned Wsm[32 * 72];
    __shared__ float Bs[64], SC[64], SH[64];
    __shared__ float redS[8][32], redQ[8][32];

    const int tid = threadIdx.x;
    const int row0 = blockIdx.x * 64;

    if (tid < 64) {
        Bs[tid] = b[tid];
        if (applyBNin) {
            float invN = 1.0f / (float)N;
            float mean = statsIn[tid] * invN;
            float var  = statsIn[64 + tid] * invN - mean * mean;
            float sc = gamma[tid] * rsqrtf(var + 1e-5f);
            SC[tid] = sc;
            SH[tid] = beta[tid] - mean * sc;
        }
    }
    __syncthreads();

    #pragma unroll
    for (int it = 0; it < 2; it++) {
        int idx = tid + it * 256;
        int k2 = idx >> 4, nq = idx & 15;
        uint4 u = ((const uint4*)Wh)[k2 * 16 + nq];
        *(uint4*)&Wsm[k2 * 72 + nq * 4] = u;
    }
    if (inH) {
        #pragma unroll
        for (int it = 0; it < 2; it++) {
            int idx = tid + it * 256;
            int row = idx >> 3, w4 = idx & 7;
            int gr = row0 + row;
            uint4 u = make_uint4(0u, 0u, 0u, 0u);
            if (gr < N) u = inH[(size_t)gr * 8 + w4];
            *(uint4*)&Xs[row * 68 + w4 * 4] = u;
        }
    } else {
        #pragma unroll
        for (int it = 0; it < 8; it++) {
            int idx = tid + it * 256;
            int row = idx >> 5, k2 = idx & 31;
            int gr = row0 + row;
            float2 v = make_float2(0.f, 0.f);
            if (gr < N) v = ((const float2*)inF)[(size_t)gr * 32 + k2];
            if (applyBNin) {
                int c = k2 * 2;
                v.x = fmaxf(fmaf(v.x, SC[c], SH[c]), 0.f);
                v.y = fmaxf(fmaf(v.y, SC[c + 1], SH[c + 1]), 0.f);
            }
            __half2 h = __floats2half2_rn(v.x, v.y);
            Xs[row * 68 + k2] = *(unsigned*)&h;
        }
    }
    __syncthreads();

    const int w = tid >> 5, lane = tid & 31;
    const int ms = w & 3, nh = w >> 2;
    const int g = lane >> 2, t4 = lane & 3;
    const int mbase = ms * 16;
    const int nbase = nh * 32;

    float c_[4][4];
    #pragma unroll
    for (int nt = 0; nt < 4; nt++) {
        int col0 = nbase + nt * 8 + 2 * t4;
        c_[nt][0] = Bs[col0]; c_[nt][1] = Bs[col0 + 1];
        c_[nt][2] = Bs[col0]; c_[nt][3] = Bs[col0 + 1];
    }

    #pragma unroll
    for (int kk = 0; kk < 4; kk++) {
        int kb = kk * 8;
        unsigned A0 = Xs[(mbase + g) * 68 + kb + t4];
        unsigned A1 = Xs[(mbase + g + 8) * 68 + kb + t4];
        unsigned A2 = Xs[(mbase + g) * 68 + kb + t4 + 4];
        unsigned A3 = Xs[(mbase + g + 8) * 68 + kb + t4 + 4];
        #pragma unroll
        for (int nt = 0; nt < 4; nt++) {
            int n = nbase + nt * 8 + g;
            unsigned B0 = Wsm[(kb + t4) * 72 + n];
            unsigned B1 = Wsm[(kb + t4 + 4) * 72 + n];
            MMA_F16(c_[nt], A0, A1, A2, A3, B0, B1);
        }
    }

    int rg0 = row0 + mbase + g;
    int rg8 = rg0 + 8;
    #pragma unroll
    for (int nt = 0; nt < 4; nt++) {
        int col0 = nbase + nt * 8 + 2 * t4;
        float s0 = 0.f, s1 = 0.f, q0 = 0.f, q1 = 0.f;
        if (rg0 < N) {
            *(float2*)&out[(size_t)rg0 * 64 + col0] = make_float2(c_[nt][0], c_[nt][1]);
            s0 += c_[nt][0]; s1 += c_[nt][1];
            q0 += c_[nt][0] * c_[nt][0]; q1 += c_[nt][1] * c_[nt][1];
        }
        if (rg8 < N) {
            *(float2*)&out[(size_t)rg8 * 64 + col0] = make_float2(c_[nt][2], c_[nt][3]);
            s0 += c_[nt][2]; s1 += c_[nt][3];
            q0 += c_[nt][2] * c_[nt][2]; q1 += c_[nt][3] * c_[nt][3];
        }
        #pragma unroll
        for (int o = 16; o >= 4; o >>= 1) {
            s0 += __shfl_down_sync(0xFFFFFFFFu, s0, o);
            s1 += __shfl_down_sync(0xFFFFFFFFu, s1, o);
            q0 += __shfl_down_sync(0xFFFFFFFFu, q0, o);
            q1 += __shfl_down_sync(0xFFFFFFFFu, q1, o);
        }
        if (lane < 4) {
            redS[w][nt * 8 + 2 * t4] = s0;
            redS[w][nt * 8 + 2 * t4 + 1] = s1;
            redQ[w][nt * 8 + 2 * t4] = q0;
            redQ[w][nt * 8 + 2 * t4 + 1] = q1;
        }
    }
    __syncthreads();
    if (tid < 64) {
        int hh = tid >> 5, lc = tid & 31;
        float s = redS[hh * 4 + 0][lc] + redS[hh * 4 + 1][lc]
                + redS[hh * 4 + 2][lc] + redS[hh * 4 + 3][lc];
        float q = redQ[hh * 4 + 0][lc] + redQ[hh * 4 + 1][lc]
                + redQ[hh * 4 + 2][lc] + redQ[hh * 4 + 3][lc];
        atomicAdd(&statsOut[tid], s);
        atomicAdd(&statsOut[64 + tid], q);
    }
}

// ---------------------------------------------------------------------------
// K_final: out = x + relu(BN(t2))
// ---------------------------------------------------------------------------
__global__ __launch_bounds__(256) void k_final(const float* __restrict__ x,
                                               const float* __restrict__ t2,
                                               const float* __restrict__ statsIn,
                                               const float* __restrict__ gamma,
                                               const float* __restrict__ beta,
                                               float* __restrict__ out, int N) {
    __shared__ float SC[64];
    __shared__ float SH[64];
    int tid = threadIdx.x;
    if (tid < 64) {
        float invN = 1.0f / (float)N;
        float mean = statsIn[tid] * invN;
        float var  = statsIn[64 + tid] * invN - mean * mean;
        float sc = gamma[tid] * rsqrtf(var + 1e-5f);
        SC[tid] = sc;
        SH[tid] = beta[tid] - mean * sc;
    }
    __syncthreads();
    int n4 = N * 16;
    for (int i = blockIdx.x * 256 + tid; i < n4; i += gridDim.x * 256) {
        int c = (i & 15) * 4;
        float4 v = ((const float4*)t2)[i];
        float4 xv = ((const float4*)x)[i];
        float4 o;
        o.x = xv.x + fmaxf(fmaf(v.x, SC[c + 0], SH[c + 0]), 0.f);
        o.y = xv.y + fmaxf(fmaf(v.y, SC[c + 1], SH[c + 1]), 0.f);
        o.z = xv.z + fmaxf(fmaf(v.z, SC[c + 2], SH[c + 2]), 0.f);
        o.w = xv.w + fmaxf(fmaf(v.w, SC[c + 3], SH[c + 3]), 0.f);
        ((float4*)out)[i] = o;
    }
}

// ---------------------------------------------------------------------------
extern "C" void kernel_launch(void* const* d_in, const int* in_sizes, int n_in,
                              void* d_out, int out_size) {
    const float* x    = (const float*)d_in[0];
    const int*   ei   = (const int*)d_in[1];
    const float* eps  = (const float*)d_in[2];
    const float* W1   = (const float*)d_in[3];
    const float* b1   = (const float*)d_in[4];
    const float* g1   = (const float*)d_in[5];
    const float* beta1= (const float*)d_in[6];
    const float* W2   = (const float*)d_in[7];
    const float* b2   = (const float*)d_in[8];
    const float* gh   = (const float*)d_in[9];
    const float* betah= (const float*)d_in[10];
    float* out = (float*)d_out;

    int N = in_sizes[0] / D;
    int E = in_sizes[1] / 2;
    if (N > MAXN) N = MAXN;
    if (E > MAXE) E = MAXE;

    float* agg;      cudaGetSymbolAddress((void**)&agg, g_agg);
    float* t1;       cudaGetSymbolAddress((void**)&t1, g_t1);
    float* stats;    cudaGetSymbolAddress((void**)&stats, g_stats);
    uint4* aggh;     cudaGetSymbolAddress((void**)&aggh, g_aggh);
    unsigned* w1h;   cudaGetSymbolAddress((void**)&w1h, g_w1h);
    unsigned* w2h;   cudaGetSymbolAddress((void**)&w2h, g_w2h);

    int prepThreads = (N * 16 > E) ? N * 16 : E;
    int nScanBlocks = (N + SCAN_BLK - 1) / SCAN_BLK;

    k_prep<<<(prepThreads + 255) / 256, 256>>>(x, ei, W1, W2, N, E);
    k_scan<<<nScanBlocks, SCAN_BLK>>>(N);
    k_fill<<<(E + 255) / 256, 256>>>(ei, E);
    k_agg<<<(N + 31) / 32, 256>>>(x, eps, N);

    int gemmBlocks = (N + 63) / 64;
    k_gemm_hmma<<<gemmBlocks, 256>>>(aggh, nullptr, w1h, b1, t1, stats,
                                     nullptr, nullptr, nullptr, N, 0);
    k_gemm_hmma<<<gemmBlocks, 256>>>(nullptr, t1, w2h, b2, agg, stats + 128,
                                     stats, g1, beta1, N, 1);

    k_final<<<(N * 16 + 255) / 256, 256>>>(x, agg, stats + 128, gh, betah, out, N);
}

// round 14
// speedup vs baseline: 1.2183x; 1.0165x over previous
#include <cuda_runtime.h>
#include <cuda_fp16.h>
#include <cstdint>

#define D 64
#define MAXN 100000
#define MAXE 1600000
#define SCAN_BLK 1024

// Scratch (device globals — no allocation allowed)
__device__ float    g_agg[MAXN * D];     // gemm2 output (t2)
__device__ float    g_t1[MAXN * D];      // gemm1 output
__device__ float    g_stats[256];        // sum1, sq1, sum2, sq2
__device__ uint2    g_xh[MAXN * 16];     // x staged fp16 (gather source)
__device__ uint4    g_aggh[MAXN * 8];    // agg result, packed fp16 rows
__device__ unsigned g_w1h[32 * 64];      // W1 fp16 [k2][n] half2(k-pair)
__device__ unsigned g_w2h[32 * 64];      // W2 fp16 [k2][n]
__device__ int      g_cnt[MAXN + SCAN_BLK];
__device__ int      g_start[MAXN + 1];
__device__ int      g_epos[MAXE];        // per-edge within-dst rank (from hist)
__device__ int      g_srcs[MAXE];
__device__ int      g_bsum[SCAN_BLK];
__device__ int      g_ctr, g_ctr2;

// ---------------------------------------------------------------------------
// K_prep: stage x fp16 + degree hist (recording per-edge rank) + zero stats
//         + W1/W2 -> fp16 [k2][n]
// ---------------------------------------------------------------------------
__global__ __launch_bounds__(256) void k_prep(const float* __restrict__ x,
                                              const int* __restrict__ ei,
                                              const float* __restrict__ W1,
                                              const float* __restrict__ W2,
                                              int N, int E) {
    int i = blockIdx.x * 256 + threadIdx.x;
    if (i < 256) g_stats[i] = 0.f;
    if (i == 0) g_start[N] = E;
    if (i < 2048) {
        int k2 = i >> 6, n = i & 63;
        __half2 h = __floats2half2_rn(W1[(2 * k2) * 64 + n], W1[(2 * k2 + 1) * 64 + n]);
        g_w1h[k2 * 64 + n] = *(unsigned*)&h;
    } else if (i < 4096) {
        int j = i - 2048;
        int k2 = j >> 6, n = j & 63;
        __half2 h = __floats2half2_rn(W2[(2 * k2) * 64 + n], W2[(2 * k2 + 1) * 64 + n]);
        g_w2h[k2 * 64 + n] = *(unsigned*)&h;
    }
    if (i < E) g_epos[i] = atomicAdd(&g_cnt[ei[E + i]], 1);
    int n4 = N * 16;
    if (i >= n4) return;
    float4 v = ((const float4*)x)[i];
    __half2 h0 = __floats2half2_rn(v.x, v.y);
    __half2 h1 = __floats2half2_rn(v.z, v.w);
    uint2 u;
    u.x = *(unsigned*)&h0;
    u.y = *(unsigned*)&h1;
    g_xh[i] = u;
}

__device__ __forceinline__ int block_scan_1024(int v, int* warpsum, int* total) {
    int lane = threadIdx.x & 31, wid = threadIdx.x >> 5;
    int inc = v;
    #pragma unroll
    for (int o = 1; o < 32; o <<= 1) {
        int u = __shfl_up_sync(0xFFFFFFFFu, inc, o);
        if (lane >= o) inc += u;
    }
    if (lane == 31) warpsum[wid] = inc;
    __syncthreads();
    if (wid == 0) {
        int w = warpsum[lane];
        #pragma unroll
        for (int o = 1; o < 32; o <<= 1) {
            int u = __shfl_up_sync(0xFFFFFFFFu, w, o);
            if (lane >= o) w += u;
        }
        warpsum[lane] = w;
    }
    __syncthreads();
    int base = (wid > 0) ? warpsum[wid - 1] : 0;
    *total = warpsum[31];
    return inc + base;
}

// K_scan: single-kernel exclusive scan (resident grid, verified)
__global__ __launch_bounds__(SCAN_BLK) void k_scan(int N) {
    __shared__ int warpsum[32];
    __shared__ int s_base;
    int gi = blockIdx.x * SCAN_BLK + threadIdx.x;
    int v = (gi < N) ? g_cnt[gi] : 0;
    if (gi < N) g_cnt[gi] = 0;
    int total;
    int incl = block_scan_1024(v, warpsum, &total);

    if (threadIdx.x == 0) {
        g_bsum[blockIdx.x] = total;
        __threadfence();
        atomicAdd(&g_ctr, 1);
        while (atomicAdd(&g_ctr, 0) < (int)gridDim.x) {}
        __threadfence();
    }
    __syncthreads();

    if (threadIdx.x < 32) {
        int base = 0;
        for (int j = threadIdx.x; j < (int)blockIdx.x; j += 32) base += g_bsum[j];
        #pragma unroll
        for (int o = 16; o >= 1; o >>= 1) base += __shfl_down_sync(0xFFFFFFFFu, base, o);
        if (threadIdx.x == 0) s_base = base;
    }
    __syncthreads();

    if (gi < N) g_start[gi] = s_base + incl - v;
    if (threadIdx.x == 0) {
        int done = atomicAdd(&g_ctr2, 1);
        if (done == (int)gridDim.x - 1) { g_ctr = 0; g_ctr2 = 0; }
    }
}

// K_fill: atomic-free — pos = start[dst] + precomputed rank
__global__ __launch_bounds__(256) void k_fill(const int* __restrict__ ei, int E) {
    int e = blockIdx.x * 256 + threadIdx.x;
    if (e >= E) return;
    int src = ei[e];
    int dst = ei[E + e];
    g_srcs[g_start[dst] + g_epos[e]] = src;
}

// ---------------------------------------------------------------------------
// K_agg: (1+eps)*x[i](fp32) + fp16 neighbor sum via depth-2 HADD2 tree
// (4 edges/iter), output packed fp16 rows. fp32 accumulator chain unchanged.
// ---------------------------------------------------------------------------
__global__ __launch_bounds__(256) void k_agg(const float* __restrict__ x,
                                             const float* __restrict__ epsp,
                                             int N) {
    int tid = threadIdx.x;
    int i = blockIdx.x * 32 + (tid >> 3);
    int q = tid & 7;
    if (i >= N) return;
    float s = 1.0f + epsp[0];
    float4 x0 = ((const float4*)x)[(size_t)i * 16 + q * 2];
    float4 x1 = ((const float4*)x)[(size_t)i * 16 + q * 2 + 1];
    float4 acc0 = make_float4(x0.x * s, x0.y * s, x0.z * s, x0.w * s);
    float4 acc1 = make_float4(x1.x * s, x1.y * s, x1.z * s, x1.w * s);
    int j = g_start[i];
    int je = g_start[i + 1];
    const uint4* xh4 = (const uint4*)g_xh;
    for (; j + 4 <= je; j += 4) {
        int s0 = g_srcs[j],     s1 = g_srcs[j + 1];
        int s2 = g_srcs[j + 2], s3 = g_srcs[j + 3];
        uint4 u0 = xh4[(size_t)s0 * 8 + q];
        uint4 u1 = xh4[(size_t)s1 * 8 + q];
        uint4 u2 = xh4[(size_t)s2 * 8 + q];
        uint4 u3 = xh4[(size_t)s3 * 8 + q];
        __half2 a0 = __hadd2(*(__half2*)&u0.x, *(__half2*)&u1.x);
        __half2 a1 = __hadd2(*(__half2*)&u0.y, *(__half2*)&u1.y);
        __half2 a2 = __hadd2(*(__half2*)&u0.z, *(__half2*)&u1.z);
        __half2 a3 = __hadd2(*(__half2*)&u0.w, *(__half2*)&u1.w);
        __half2 b0 = __hadd2(*(__half2*)&u2.x, *(__half2*)&u3.x);
        __half2 b1 = __hadd2(*(__half2*)&u2.y, *(__half2*)&u3.y);
        __half2 b2 = __hadd2(*(__half2*)&u2.z, *(__half2*)&u3.z);
        __half2 b3 = __hadd2(*(__half2*)&u2.w, *(__half2*)&u3.w);
        __half2 p0 = __hadd2(a0, b0);
        __half2 p1 = __hadd2(a1, b1);
        __half2 p2 = __hadd2(a2, b2);
        __half2 p3 = __hadd2(a3, b3);
        float2 f0 = __half22float2(p0);
        float2 f1 = __half22float2(p1);
        float2 f2 = __half22float2(p2);
        float2 f3 = __half22float2(p3);
        acc0.x += f0.x; acc0.y += f0.y; acc0.z += f1.x; acc0.w += f1.y;
        acc1.x += f2.x; acc1.y += f2.y; acc1.z += f3.x; acc1.w += f3.y;
    }
    if (j + 2 <= je) {
        int s0 = g_srcs[j], s1 = g_srcs[j + 1];
        uint4 u0 = xh4[(size_t)s0 * 8 + q];
        uint4 u1 = xh4[(size_t)s1 * 8 + q];
        __half2 p0 = __hadd2(*(__half2*)&u0.x, *(__half2*)&u1.x);
        __half2 p1 = __hadd2(*(__half2*)&u0.y, *(__half2*)&u1.y);
        __half2 p2 = __hadd2(*(__half2*)&u0.z, *(__half2*)&u1.z);
        __half2 p3 = __hadd2(*(__half2*)&u0.w, *(__half2*)&u1.w);
        float2 f0 = __half22float2(p0);
        float2 f1 = __half22float2(p1);
        float2 f2 = __half22float2(p2);
        float2 f3 = __half22float2(p3);
        acc0.x += f0.x; acc0.y += f0.y; acc0.z += f1.x; acc0.w += f1.y;
        acc1.x += f2.x; acc1.y += f2.y; acc1.z += f3.x; acc1.w += f3.y;
        j += 2;
    }
    if (j < je) {
        uint4 u = xh4[(size_t)g_srcs[j] * 8 + q];
        float2 f0 = __half22float2(*(__half2*)&u.x);
        float2 f1 = __half22float2(*(__half2*)&u.y);
        float2 f2 = __half22float2(*(__half2*)&u.z);
        float2 f3 = __half22float2(*(__half2*)&u.w);
        acc0.x += f0.x; acc0.y += f0.y; acc0.z += f1.x; acc0.w += f1.y;
        acc1.x += f2.x; acc1.y += f2.y; acc1.z += f3.x; acc1.w += f3.y;
    }
    __half2 h0 = __floats2half2_rn(acc0.x, acc0.y);
    __half2 h1 = __floats2half2_rn(acc0.z, acc0.w);
    __half2 h2 = __floats2half2_rn(acc1.x, acc1.y);
    __half2 h3 = __floats2half2_rn(acc1.z, acc1.w);
    uint4 o;
    o.x = *(unsigned*)&h0; o.y = *(unsigned*)&h1;
    o.z = *(unsigned*)&h2; o.w = *(unsigned*)&h3;
    g_aggh[(size_t)i * 8 + q] = o;
}

// ---------------------------------------------------------------------------
// fp16 HMMA GEMM + fused BN stats (R12 verified version)
// ---------------------------------------------------------------------------
#define MMA_F16(c, a0, a1, a2, a3, b0, b1)                                    \
    asm volatile(                                                             \
        "mma.sync.aligned.m16n8k16.row.col.f32.f16.f16.f32 "                  \
        "{%0,%1,%2,%3}, {%4,%5,%6,%7}, {%8,%9}, {%0,%1,%2,%3};"               \
        : "+f"(c[0]), "+f"(c[1]), "+f"(c[2]), "+f"(c[3])                      \
        : "r"(a0), "r"(a1), "r"(a2), "r"(a3), "r"(b0), "r"(b1))

__global__ __launch_bounds__(256) void k_gemm_hmma(
    const uint4* __restrict__ inH, const float* __restrict__ inF,
    const unsigned* __restrict__ Wh,
    const float* __restrict__ b, float* __restrict__ out,
    float* __restrict__ statsOut,
    const float* __restrict__ statsIn,
    const float* __restrict__ gamma, const float* __restrict__ beta,
    int N, int applyBNin)
{
    __shared__ unsigned Xs[64 * 68];
    __shared__ unsigned Wsm[32 * 72];
    __shared__ float Bs[64], SC[64], SH[64];
    __shared__ float redS[8][32], redQ[8][32];

    const int tid = threadIdx.x;
    const int row0 = blockIdx.x * 64;

    if (tid < 64) {
        Bs[tid] = b[tid];
        if (applyBNin) {
            float invN = 1.0f / (float)N;
            float mean = statsIn[tid] * invN;
            float var  = statsIn[64 + tid] * invN - mean * mean;
            float sc = gamma[tid] * rsqrtf(var + 1e-5f);
            SC[tid] = sc;
            SH[tid] = beta[tid] - mean * sc;
        }
    }
    __syncthreads();

    #pragma unroll
    for (int it = 0; it < 2; it++) {
        int idx = tid + it * 256;
        int k2 = idx >> 4, nq = idx & 15;
        uint4 u = ((const uint4*)Wh)[k2 * 16 + nq];
        *(uint4*)&Wsm[k2 * 72 + nq * 4] = u;
    }
    if (inH) {
        #pragma unroll
        for (int it = 0; it < 2; it++) {
            int idx = tid + it * 256;
            int row = idx >> 3, w4 = idx & 7;
            int gr = row0 + row;
            uint4 u = make_uint4(0u, 0u, 0u, 0u);
            if (gr < N) u = inH[(size_t)gr * 8 + w4];
            *(uint4*)&Xs[row * 68 + w4 * 4] = u;
        }
    } else {
        #pragma unroll
        for (int it = 0; it < 8; it++) {
            int idx = tid + it * 256;
            int row = idx >> 5, k2 = idx & 31;
            int gr = row0 + row;
            float2 v = make_float2(0.f, 0.f);
            if (gr < N) v = ((const float2*)inF)[(size_t)gr * 32 + k2];
            if (applyBNin) {
                int c = k2 * 2;
                v.x = fmaxf(fmaf(v.x, SC[c], SH[c]), 0.f);
                v.y = fmaxf(fmaf(v.y, SC[c + 1], SH[c + 1]), 0.f);
            }
            __half2 h = __floats2half2_rn(v.x, v.y);
            Xs[row * 68 + k2] = *(unsigned*)&h;
        }
    }
    __syncthreads();

    const int w = tid >> 5, lane = tid & 31;
    const int ms = w & 3, nh = w >> 2;
    const int g = lane >> 2, t4 = lane & 3;
    const int mbase = ms * 16;
    const int nbase = nh * 32;

    float c_[4][4];
    #pragma unroll
    for (int nt = 0; nt < 4; nt++) {
        int col0 = nbase + nt * 8 + 2 * t4;
        c_[nt][0] = Bs[col0]; c_[nt][1] = Bs[col0 + 1];
        c_[nt][2] = Bs[col0]; c_[nt][3] = Bs[col0 + 1];
    }

    #pragma unroll
    for (int kk = 0; kk < 4; kk++) {
        int kb = kk * 8;
        unsigned A0 = Xs[(mbase + g) * 68 + kb + t4];
        unsigned A1 = Xs[(mbase + g + 8) * 68 + kb + t4];
        unsigned A2 = Xs[(mbase + g) * 68 + kb + t4 + 4];
        unsigned A3 = Xs[(mbase + g + 8) * 68 + kb + t4 + 4];
        #pragma unroll
        for (int nt = 0; nt < 4; nt++) {
            int n = nbase + nt * 8 + g;
            unsigned B0 = Wsm[(kb + t4) * 72 + n];
            unsigned B1 = Wsm[(kb + t4 + 4) * 72 + n];
            MMA_F16(c_[nt], A0, A1, A2, A3, B0, B1);
        }
    }

    int rg0 = row0 + mbase + g;
    int rg8 = rg0 + 8;
    #pragma unroll
    for (int nt = 0; nt < 4; nt++) {
        int col0 = nbase + nt * 8 + 2 * t4;
        float s0 = 0.f, s1 = 0.f, q0 = 0.f, q1 = 0.f;
        if (rg0 < N) {
            *(float2*)&out[(size_t)rg0 * 64 + col0] = make_float2(c_[nt][0], c_[nt][1]);
            s0 += c_[nt][0]; s1 += c_[nt][1];
            q0 += c_[nt][0] * c_[nt][0]; q1 += c_[nt][1] * c_[nt][1];
        }
        if (rg8 < N) {
            *(float2*)&out[(size_t)rg8 * 64 + col0] = make_float2(c_[nt][2], c_[nt][3]);
            s0 += c_[nt][2]; s1 += c_[nt][3];
            q0 += c_[nt][2] * c_[nt][2]; q1 += c_[nt][3] * c_[nt][3];
        }
        #pragma unroll
        for (int o = 16; o >= 4; o >>= 1) {
            s0 += __shfl_down_sync(0xFFFFFFFFu, s0, o);
            s1 += __shfl_down_sync(0xFFFFFFFFu, s1, o);
            q0 += __shfl_down_sync(0xFFFFFFFFu, q0, o);
            q1 += __shfl_down_sync(0xFFFFFFFFu, q1, o);
        }
        if (lane < 4) {
            redS[w][nt * 8 + 2 * t4] = s0;
            redS[w][nt * 8 + 2 * t4 + 1] = s1;
            redQ[w][nt * 8 + 2 * t4] = q0;
            redQ[w][nt * 8 + 2 * t4 + 1] = q1;
        }
    }
    __syncthreads();
    if (tid < 64) {
        int hh = tid >> 5, lc = tid & 31;
        float s = redS[hh * 4 + 0][lc] + redS[hh * 4 + 1][lc]
                + redS[hh * 4 + 2][lc] + redS[hh * 4 + 3][lc];
        float q = redQ[hh * 4 + 0][lc] + redQ[hh * 4 + 1][lc]
                + redQ[hh * 4 + 2][lc] + redQ[hh * 4 + 3][lc];
        atomicAdd(&statsOut[tid], s);
        atomicAdd(&statsOut[64 + tid], q);
    }
}

// ---------------------------------------------------------------------------
// K_final: out = x + relu(BN(t2))
// ---------------------------------------------------------------------------
__global__ __launch_bounds__(256) void k_final(const float* __restrict__ x,
                                               const float* __restrict__ t2,
                                               const float* __restrict__ statsIn,
                                               const float* __restrict__ gamma,
                                               const float* __restrict__ beta,
                                               float* __restrict__ out, int N) {
    __shared__ float SC[64];
    __shared__ float SH[64];
    int tid = threadIdx.x;
    if (tid < 64) {
        float invN = 1.0f / (float)N;
        float mean = statsIn[tid] * invN;
        float var  = statsIn[64 + tid] * invN - mean * mean;
        float sc = gamma[tid] * rsqrtf(var + 1e-5f);
        SC[tid] = sc;
        SH[tid] = beta[tid] - mean * sc;
    }
    __syncthreads();
    int n4 = N * 16;
    for (int i = blockIdx.x * 256 + tid; i < n4; i += gridDim.x * 256) {
        int c = (i & 15) * 4;
        float4 v = ((const float4*)t2)[i];
        float4 xv = ((const float4*)x)[i];
        float4 o;
        o.x = xv.x + fmaxf(fmaf(v.x, SC[c + 0], SH[c + 0]), 0.f);
        o.y = xv.y + fmaxf(fmaf(v.y, SC[c + 1], SH[c + 1]), 0.f);
        o.z = xv.z + fmaxf(fmaf(v.z, SC[c + 2], SH[c + 2]), 0.f);
        o.w = xv.w + fmaxf(fmaf(v.w, SC[c + 3], SH[c + 3]), 0.f);
        ((float4*)out)[i] = o;
    }
}

// ---------------------------------------------------------------------------
extern "C" void kernel_launch(void* const* d_in, const int* in_sizes, int n_in,
                              void* d_out, int out_size) {
    const float* x    = (const float*)d_in[0];
    const int*   ei   = (const int*)d_in[1];
    const float* eps  = (const float*)d_in[2];
    const float* W1   = (const float*)d_in[3];
    const float* b1   = (const float*)d_in[4];
    const float* g1   = (const float*)d_in[5];
    const float* beta1= (const float*)d_in[6];
    const float* W2   = (const float*)d_in[7];
    const float* b2   = (const float*)d_in[8];
    const float* gh   = (const float*)d_in[9];
    const float* betah= (const float*)d_in[10];
    float* out = (float*)d_out;

    int N = in_sizes[0] / D;
    int E = in_sizes[1] / 2;
    if (N > MAXN) N = MAXN;
    if (E > MAXE) E = MAXE;

    float* agg;      cudaGetSymbolAddress((void**)&agg, g_agg);
    float* t1;       cudaGetSymbolAddress((void**)&t1, g_t1);
    float* stats;    cudaGetSymbolAddress((void**)&stats, g_stats);
    uint4* aggh;     cudaGetSymbolAddress((void**)&aggh, g_aggh);
    unsigned* w1h;   cudaGetSymbolAddress((void**)&w1h, g_w1h);
    unsigned* w2h;   cudaGetSymbolAddress((void**)&w2h, g_w2h);

    int prepThreads = (N * 16 > E) ? N * 16 : E;
    int nScanBlocks = (N + SCAN_BLK - 1) / SCAN_BLK;

    k_prep<<<(prepThreads + 255) / 256, 256>>>(x, ei, W1, W2, N, E);
    k_scan<<<nScanBlocks, SCAN_BLK>>>(N);
    k_fill<<<(E + 255) / 256, 256>>>(ei, E);
    k_agg<<<(N + 31) / 32, 256>>>(x, eps, N);

    int gemmBlocks = (N + 63) / 64;
    k_gemm_hmma<<<gemmBlocks, 256>>>(aggh, nullptr, w1h, b1, t1, stats,
                                     nullptr, nullptr, nullptr, N, 0);
    k_gemm_hmma<<<gemmBlocks, 256>>>(nullptr, t1, w2h, b2, agg, stats + 128,
                                     stats, g1, beta1, N, 1);

    k_final<<<(N * 16 + 255) / 256, 256>>>(x, agg, stats + 128, gh, betah, out, N);
}

// round 15
// speedup vs baseline: 1.2436x; 1.0207x over previous
#include <cuda_runtime.h>
#include <cuda_fp16.h>
#include <cstdint>

#define D 64
#define MAXN 100000
#define MAXE 1600000
#define SCAN_BLK 1024

// Scratch (device globals — no allocation allowed)
__device__ float    g_agg[MAXN * D];     // gemm2 output (t2, fp32 for k_final)
__device__ float    g_stats[256];        // sum1, sq1, sum2, sq2
__device__ uint2    g_xh[MAXN * 16];     // x staged fp16 (gather source)
__device__ uint4    g_aggh[MAXN * 8];    // agg result, packed fp16 rows
__device__ uint4    g_t1h[MAXN * 8];     // t1 (gemm1 out), packed fp16 rows
__device__ unsigned g_w1h[32 * 64];      // W1 fp16 [k2][n] half2(k-pair)
__device__ unsigned g_w2h[32 * 64];      // W2 fp16 [k2][n]
__device__ int      g_cnt[MAXN + SCAN_BLK];
__device__ int      g_start[MAXN + 1];
__device__ int      g_epos[MAXE];        // per-edge within-dst rank
__device__ int      g_srcs[MAXE];
__device__ int      g_bsum[SCAN_BLK];
__device__ int      g_ctr, g_ctr2;

// ---------------------------------------------------------------------------
// K_prep: stage x fp16 + degree hist (record per-edge rank) + zero stats
//         + W1/W2 -> fp16 [k2][n]
// ---------------------------------------------------------------------------
__global__ __launch_bounds__(256) void k_prep(const float* __restrict__ x,
                                              const int* __restrict__ ei,
                                              const float* __restrict__ W1,
                                              const float* __restrict__ W2,
                                              int N, int E) {
    int i = blockIdx.x * 256 + threadIdx.x;
    if (i < 256) g_stats[i] = 0.f;
    if (i == 0) g_start[N] = E;
    if (i < 2048) {
        int k2 = i >> 6, n = i & 63;
        __half2 h = __floats2half2_rn(W1[(2 * k2) * 64 + n], W1[(2 * k2 + 1) * 64 + n]);
        g_w1h[k2 * 64 + n] = *(unsigned*)&h;
    } else if (i < 4096) {
        int j = i - 2048;
        int k2 = j >> 6, n = j & 63;
        __half2 h = __floats2half2_rn(W2[(2 * k2) * 64 + n], W2[(2 * k2 + 1) * 64 + n]);
        g_w2h[k2 * 64 + n] = *(unsigned*)&h;
    }
    if (i < E) g_epos[i] = atomicAdd(&g_cnt[ei[E + i]], 1);
    int n4 = N * 16;
    if (i >= n4) return;
    float4 v = ((const float4*)x)[i];
    __half2 h0 = __floats2half2_rn(v.x, v.y);
    __half2 h1 = __floats2half2_rn(v.z, v.w);
    uint2 u;
    u.x = *(unsigned*)&h0;
    u.y = *(unsigned*)&h1;
    g_xh[i] = u;
}

__device__ __forceinline__ int block_scan_1024(int v, int* warpsum, int* total) {
    int lane = threadIdx.x & 31, wid = threadIdx.x >> 5;
    int inc = v;
    #pragma unroll
    for (int o = 1; o < 32; o <<= 1) {
        int u = __shfl_up_sync(0xFFFFFFFFu, inc, o);
        if (lane >= o) inc += u;
    }
    if (lane == 31) warpsum[wid] = inc;
    __syncthreads();
    if (wid == 0) {
        int w = warpsum[lane];
        #pragma unroll
        for (int o = 1; o < 32; o <<= 1) {
            int u = __shfl_up_sync(0xFFFFFFFFu, w, o);
            if (lane >= o) w += u;
        }
        warpsum[lane] = w;
    }
    __syncthreads();
    int base = (wid > 0) ? warpsum[wid - 1] : 0;
    *total = warpsum[31];
    return inc + base;
}

// K_scan: single-kernel exclusive scan (resident grid, verified)
__global__ __launch_bounds__(SCAN_BLK) void k_scan(int N) {
    __shared__ int warpsum[32];
    __shared__ int s_base;
    int gi = blockIdx.x * SCAN_BLK + threadIdx.x;
    int v = (gi < N) ? g_cnt[gi] : 0;
    if (gi < N) g_cnt[gi] = 0;
    int total;
    int incl = block_scan_1024(v, warpsum, &total);

    if (threadIdx.x == 0) {
        g_bsum[blockIdx.x] = total;
        __threadfence();
        atomicAdd(&g_ctr, 1);
        while (atomicAdd(&g_ctr, 0) < (int)gridDim.x) {}
        __threadfence();
    }
    __syncthreads();

    if (threadIdx.x < 32) {
        int base = 0;
        for (int j = threadIdx.x; j < (int)blockIdx.x; j += 32) base += g_bsum[j];
        #pragma unroll
        for (int o = 16; o >= 1; o >>= 1) base += __shfl_down_sync(0xFFFFFFFFu, base, o);
        if (threadIdx.x == 0) s_base = base;
    }
    __syncthreads();

    if (gi < N) g_start[gi] = s_base + incl - v;
    if (threadIdx.x == 0) {
        int done = atomicAdd(&g_ctr2, 1);
        if (done == (int)gridDim.x - 1) { g_ctr = 0; g_ctr2 = 0; }
    }
}

// K_fill: atomic-free — pos = start[dst] + precomputed rank
__global__ __launch_bounds__(256) void k_fill(const int* __restrict__ ei, int E) {
    int e = blockIdx.x * 256 + threadIdx.x;
    if (e >= E) return;
    int src = ei[e];
    int dst = ei[E + e];
    g_srcs[g_start[dst] + g_epos[e]] = src;
}

// ---------------------------------------------------------------------------
// K_agg: (1+eps)*x[i](fp32) + fp16 neighbor sum via depth-2 HADD2 tree
// (R14 verified version)
// ---------------------------------------------------------------------------
__global__ __launch_bounds__(256) void k_agg(const float* __restrict__ x,
                                             const float* __restrict__ epsp,
                                             int N) {
    int tid = threadIdx.x;
    int i = blockIdx.x * 32 + (tid >> 3);
    int q = tid & 7;
    if (i >= N) return;
    float s = 1.0f + epsp[0];
    float4 x0 = ((const float4*)x)[(size_t)i * 16 + q * 2];
    float4 x1 = ((const float4*)x)[(size_t)i * 16 + q * 2 + 1];
    float4 acc0 = make_float4(x0.x * s, x0.y * s, x0.z * s, x0.w * s);
    float4 acc1 = make_float4(x1.x * s, x1.y * s, x1.z * s, x1.w * s);
    int j = g_start[i];
    int je = g_start[i + 1];
    const uint4* xh4 = (const uint4*)g_xh;
    for (; j + 4 <= je; j += 4) {
        int s0 = g_srcs[j],     s1 = g_srcs[j + 1];
        int s2 = g_srcs[j + 2], s3 = g_srcs[j + 3];
        uint4 u0 = xh4[(size_t)s0 * 8 + q];
        uint4 u1 = xh4[(size_t)s1 * 8 + q];
        uint4 u2 = xh4[(size_t)s2 * 8 + q];
        uint4 u3 = xh4[(size_t)s3 * 8 + q];
        __half2 a0 = __hadd2(*(__half2*)&u0.x, *(__half2*)&u1.x);
        __half2 a1 = __hadd2(*(__half2*)&u0.y, *(__half2*)&u1.y);
        __half2 a2 = __hadd2(*(__half2*)&u0.z, *(__half2*)&u1.z);
        __half2 a3 = __hadd2(*(__half2*)&u0.w, *(__half2*)&u1.w);
        __half2 b0 = __hadd2(*(__half2*)&u2.x, *(__half2*)&u3.x);
        __half2 b1 = __hadd2(*(__half2*)&u2.y, *(__half2*)&u3.y);
        __half2 b2 = __hadd2(*(__half2*)&u2.z, *(__half2*)&u3.z);
        __half2 b3 = __hadd2(*(__half2*)&u2.w, *(__half2*)&u3.w);
        __half2 p0 = __hadd2(a0, b0);
        __half2 p1 = __hadd2(a1, b1);
        __half2 p2 = __hadd2(a2, b2);
        __half2 p3 = __hadd2(a3, b3);
        float2 f0 = __half22float2(p0);
        float2 f1 = __half22float2(p1);
        float2 f2 = __half22float2(p2);
        float2 f3 = __half22float2(p3);
        acc0.x += f0.x; acc0.y += f0.y; acc0.z += f1.x; acc0.w += f1.y;
        acc1.x += f2.x; acc1.y += f2.y; acc1.z += f3.x; acc1.w += f3.y;
    }
    if (j + 2 <= je) {
        int s0 = g_srcs[j], s1 = g_srcs[j + 1];
        uint4 u0 = xh4[(size_t)s0 * 8 + q];
        uint4 u1 = xh4[(size_t)s1 * 8 + q];
        __half2 p0 = __hadd2(*(__half2*)&u0.x, *(__half2*)&u1.x);
        __half2 p1 = __hadd2(*(__half2*)&u0.y, *(__half2*)&u1.y);
        __half2 p2 = __hadd2(*(__half2*)&u0.z, *(__half2*)&u1.z);
        __half2 p3 = __hadd2(*(__half2*)&u0.w, *(__half2*)&u1.w);
        float2 f0 = __half22float2(p0);
        float2 f1 = __half22float2(p1);
        float2 f2 = __half22float2(p2);
        float2 f3 = __half22float2(p3);
        acc0.x += f0.x; acc0.y += f0.y; acc0.z += f1.x; acc0.w += f1.y;
        acc1.x += f2.x; acc1.y += f2.y; acc1.z += f3.x; acc1.w += f3.y;
        j += 2;
    }
    if (j < je) {
        uint4 u = xh4[(size_t)g_srcs[j] * 8 + q];
        float2 f0 = __half22float2(*(__half2*)&u.x);
        float2 f1 = __half22float2(*(__half2*)&u.y);
        float2 f2 = __half22float2(*(__half2*)&u.z);
        float2 f3 = __half22float2(*(__half2*)&u.w);
        acc0.x += f0.x; acc0.y += f0.y; acc0.z += f1.x; acc0.w += f1.y;
        acc1.x += f2.x; acc1.y += f2.y; acc1.z += f3.x; acc1.w += f3.y;
    }
    __half2 h0 = __floats2half2_rn(acc0.x, acc0.y);
    __half2 h1 = __floats2half2_rn(acc0.z, acc0.w);
    __half2 h2 = __floats2half2_rn(acc1.x, acc1.y);
    __half2 h3 = __floats2half2_rn(acc1.z, acc1.w);
    uint4 o;
    o.x = *(unsigned*)&h0; o.y = *(unsigned*)&h1;
    o.z = *(unsigned*)&h2; o.w = *(unsigned*)&h3;
    g_aggh[(size_t)i * 8 + q] = o;
}

// ---------------------------------------------------------------------------
// fp16 HMMA GEMM + fused BN stats.
// mode 0: inH staged by raw uint4 copy (no BN).
// mode 1: inH staged with fp16 BN+ReLU (HFMA2/HMAX2, half2 scale/shift).
// outF (fp32) and/or outH (packed fp16) written if non-null.
// ---------------------------------------------------------------------------
#define MMA_F16(c, a0, a1, a2, a3, b0, b1)                                    \
    asm volatile(                                                             \
        "mma.sync.aligned.m16n8k16.row.col.f32.f16.f16.f32 "                  \
        "{%0,%1,%2,%3}, {%4,%5,%6,%7}, {%8,%9}, {%0,%1,%2,%3};"               \
        : "+f"(c[0]), "+f"(c[1]), "+f"(c[2]), "+f"(c[3])                      \
        : "r"(a0), "r"(a1), "r"(a2), "r"(a3), "r"(b0), "r"(b1))

__global__ __launch_bounds__(256) void k_gemm_hmma(
    const uint4* __restrict__ inH,
    const unsigned* __restrict__ Wh,
    const float* __restrict__ b,
    float* __restrict__ outF, unsigned* __restrict__ outH,
    float* __restrict__ statsOut,
    const float* __restrict__ statsIn,
    const float* __restrict__ gamma, const float* __restrict__ beta,
    int N, int mode)
{
    __shared__ unsigned Xs[64 * 68];
    __shared__ unsigned Wsm[32 * 72];
    __shared__ float Bs[64], SC[64], SH[64];
    __shared__ unsigned SCH[32], SHH[32];   // half2 per column pair
    __shared__ float redS[8][32], redQ[8][32];

    const int tid = threadIdx.x;
    const int row0 = blockIdx.x * 64;

    if (tid < 64) {
        Bs[tid] = b[tid];
        if (mode == 1) {
            float invN = 1.0f / (float)N;
            float mean = statsIn[tid] * invN;
            float var  = statsIn[64 + tid] * invN - mean * mean;
            float sc = gamma[tid] * rsqrtf(var + 1e-5f);
            SC[tid] = sc;
            SH[tid] = beta[tid] - mean * sc;
        }
    }
    __syncthreads();
    if (mode == 1 && tid < 32) {
        __half2 hsc = __floats2half2_rn(SC[2 * tid], SC[2 * tid + 1]);
        __half2 hsh = __floats2half2_rn(SH[2 * tid], SH[2 * tid + 1]);
        SCH[tid] = *(unsigned*)&hsc;
        SHH[tid] = *(unsigned*)&hsh;
    }
    __syncthreads();

    // Stage W (pre-converted fp16, uint4 copy)
    #pragma unroll
    for (int it = 0; it < 2; it++) {
        int idx = tid + it * 256;
        int k2 = idx >> 4, nq = idx & 15;
        uint4 u = ((const uint4*)Wh)[k2 * 16 + nq];
        *(uint4*)&Wsm[k2 * 72 + nq * 4] = u;
    }
    // Stage X (packed fp16 rows; optional fp16 BN+ReLU)
    const __half2 hzero = __floats2half2_rn(0.f, 0.f);
    #pragma unroll
    for (int it = 0; it < 2; it++) {
        int idx = tid + it * 256;
        int row = idx >> 3, w4 = idx & 7;
        int gr = row0 + row;
        uint4 u = make_uint4(0u, 0u, 0u, 0u);
        if (gr < N) u = inH[(size_t)gr * 8 + w4];
        if (mode == 1) {
            int cp = w4 * 4;        // column-pair index of u.x
            __half2 r0 = __hmax2(__hfma2(*(__half2*)&u.x, *(__half2*)&SCH[cp + 0], *(__half2*)&SHH[cp + 0]), hzero);
            __half2 r1 = __hmax2(__hfma2(*(__half2*)&u.y, *(__half2*)&SCH[cp + 1], *(__half2*)&SHH[cp + 1]), hzero);
            __half2 r2 = __hmax2(__hfma2(*(__half2*)&u.z, *(__half2*)&SCH[cp + 2], *(__half2*)&SHH[cp + 2]), hzero);
            __half2 r3 = __hmax2(__hfma2(*(__half2*)&u.w, *(__half2*)&SCH[cp + 3], *(__half2*)&SHH[cp + 3]), hzero);
            u.x = *(unsigned*)&r0; u.y = *(unsigned*)&r1;
            u.z = *(unsigned*)&r2; u.w = *(unsigned*)&r3;
        }
        *(uint4*)&Xs[row * 68 + w4 * 4] = u;
    }
    __syncthreads();

    const int w = tid >> 5, lane = tid & 31;
    const int ms = w & 3, nh = w >> 2;
    const int g = lane >> 2, t4 = lane & 3;
    const int mbase = ms * 16;
    const int nbase = nh * 32;

    float c_[4][4];
    #pragma unroll
    for (int nt = 0; nt < 4; nt++) {
        int col0 = nbase + nt * 8 + 2 * t4;
        c_[nt][0] = Bs[col0]; c_[nt][1] = Bs[col0 + 1];
        c_[nt][2] = Bs[col0]; c_[nt][3] = Bs[col0 + 1];
    }

    #pragma unroll
    for (int kk = 0; kk < 4; kk++) {
        int kb = kk * 8;
        unsigned A0 = Xs[(mbase + g) * 68 + kb + t4];
        unsigned A1 = Xs[(mbase + g + 8) * 68 + kb + t4];
        unsigned A2 = Xs[(mbase + g) * 68 + kb + t4 + 4];
        unsigned A3 = Xs[(mbase + g + 8) * 68 + kb + t4 + 4];
        #pragma unroll
        for (int nt = 0; nt < 4; nt++) {
            int n = nbase + nt * 8 + g;
            unsigned B0 = Wsm[(kb + t4) * 72 + n];
            unsigned B1 = Wsm[(kb + t4 + 4) * 72 + n];
            MMA_F16(c_[nt], A0, A1, A2, A3, B0, B1);
        }
    }

    int rg0 = row0 + mbase + g;
    int rg8 = rg0 + 8;
    #pragma unroll
    for (int nt = 0; nt < 4; nt++) {
        int col0 = nbase + nt * 8 + 2 * t4;
        float s0 = 0.f, s1 = 0.f, q0 = 0.f, q1 = 0.f;
        if (rg0 < N) {
            if (outF) *(float2*)&outF[(size_t)rg0 * 64 + col0] = make_float2(c_[nt][0], c_[nt][1]);
            if (outH) {
                __half2 h = __floats2half2_rn(c_[nt][0], c_[nt][1]);
                outH[(size_t)rg0 * 32 + (col0 >> 1)] = *(unsigned*)&h;
            }
            s0 += c_[nt][0]; s1 += c_[nt][1];
            q0 += c_[nt][0] * c_[nt][0]; q1 += c_[nt][1] * c_[nt][1];
        }
        if (rg8 < N) {
            if (outF) *(float2*)&outF[(size_t)rg8 * 64 + col0] = make_float2(c_[nt][2], c_[nt][3]);
            if (outH) {
                __half2 h = __floats2half2_rn(c_[nt][2], c_[nt][3]);
                outH[(size_t)rg8 * 32 + (col0 >> 1)] = *(unsigned*)&h;
            }
            s0 += c_[nt][2]; s1 += c_[nt][3];
            q0 += c_[nt][2] * c_[nt][2]; q1 += c_[nt][3] * c_[nt][3];
        }
        #pragma unroll
        for (int o = 16; o >= 4; o >>= 1) {
            s0 += __shfl_down_sync(0xFFFFFFFFu, s0, o);
            s1 += __shfl_down_sync(0xFFFFFFFFu, s1, o);
            q0 += __shfl_down_sync(0xFFFFFFFFu, q0, o);
            q1 += __shfl_down_sync(0xFFFFFFFFu, q1, o);
        }
        if (lane < 4) {
            redS[w][nt * 8 + 2 * t4] = s0;
            redS[w][nt * 8 + 2 * t4 + 1] = s1;
            redQ[w][nt * 8 + 2 * t4] = q0;
            redQ[w][nt * 8 + 2 * t4 + 1] = q1;
        }
    }
    __syncthreads();
    if (tid < 64) {
        int hh = tid >> 5, lc = tid & 31;
        float s = redS[hh * 4 + 0][lc] + redS[hh * 4 + 1][lc]
                + redS[hh * 4 + 2][lc] + redS[hh * 4 + 3][lc];
        float q = redQ[hh * 4 + 0][lc] + redQ[hh * 4 + 1][lc]
                + redQ[hh * 4 + 2][lc] + redQ[hh * 4 + 3][lc];
        atomicAdd(&statsOut[tid], s);
        atomicAdd(&statsOut[64 + tid], q);
    }
}

// ---------------------------------------------------------------------------
// K_final: out = x + relu(BN(t2))
// ---------------------------------------------------------------------------
__global__ __launch_bounds__(256) void k_final(const float* __restrict__ x,
                                               const float* __restrict__ t2,
                                               const float* __restrict__ statsIn,
                                               const float* __restrict__ gamma,
                                               const float* __restrict__ beta,
                                               float* __restrict__ out, int N) {
    __shared__ float SC[64];
    __shared__ float SH[64];
    int tid = threadIdx.x;
    if (tid < 64) {
        float invN = 1.0f / (float)N;
        float mean = statsIn[tid] * invN;
        float var  = statsIn[64 + tid] * invN - mean * mean;
        float sc = gamma[tid] * rsqrtf(var + 1e-5f);
        SC[tid] = sc;
        SH[tid] = beta[tid] - mean * sc;
    }
    __syncthreads();
    int n4 = N * 16;
    for (int i = blockIdx.x * 256 + tid; i < n4; i += gridDim.x * 256) {
        int c = (i & 15) * 4;
        float4 v = ((const float4*)t2)[i];
        float4 xv = ((const float4*)x)[i];
        float4 o;
        o.x = xv.x + fmaxf(fmaf(v.x, SC[c + 0], SH[c + 0]), 0.f);
        o.y = xv.y + fmaxf(fmaf(v.y, SC[c + 1], SH[c + 1]), 0.f);
        o.z = xv.z + fmaxf(fmaf(v.z, SC[c + 2], SH[c + 2]), 0.f);
        o.w = xv.w + fmaxf(fmaf(v.w, SC[c + 3], SH[c + 3]), 0.f);
        ((float4*)out)[i] = o;
    }
}

// ---------------------------------------------------------------------------
extern "C" void kernel_launch(void* const* d_in, const int* in_sizes, int n_in,
                              void* d_out, int out_size) {
    const float* x    = (const float*)d_in[0];
    const int*   ei   = (const int*)d_in[1];
    const float* eps  = (const float*)d_in[2];
    const float* W1   = (const float*)d_in[3];
    const float* b1   = (const float*)d_in[4];
    const float* g1   = (const float*)d_in[5];
    const float* beta1= (const float*)d_in[6];
    const float* W2   = (const float*)d_in[7];
    const float* b2   = (const float*)d_in[8];
    const float* gh   = (const float*)d_in[9];
    const float* betah= (const float*)d_in[10];
    float* out = (float*)d_out;

    int N = in_sizes[0] / D;
    int E = in_sizes[1] / 2;
    if (N > MAXN) N = MAXN;
    if (E > MAXE) E = MAXE;

    float* agg;      cudaGetSymbolAddress((void**)&agg, g_agg);
    float* stats;    cudaGetSymbolAddress((void**)&stats, g_stats);
    uint4* aggh;     cudaGetSymbolAddress((void**)&aggh, g_aggh);
    uint4* t1h;      cudaGetSymbolAddress((void**)&t1h, g_t1h);
    unsigned* w1h;   cudaGetSymbolAddress((void**)&w1h, g_w1h);
    unsigned* w2h;   cudaGetSymbolAddress((void**)&w2h, g_w2h);

    int prepThreads = (N * 16 > E) ? N * 16 : E;
    int nScanBlocks = (N + SCAN_BLK - 1) / SCAN_BLK;

    k_prep<<<(prepThreads + 255) / 256, 256>>>(x, ei, W1, W2, N, E);
    k_scan<<<nScanBlocks, SCAN_BLK>>>(N);
    k_fill<<<(E + 255) / 256, 256>>>(ei, E);
    k_agg<<<(N + 31) / 32, 256>>>(x, eps, N);

    int gemmBlocks = (N + 63) / 64;
    // gemm1: in = aggh (raw fp16), out = t1h (fp16), stats1
    k_gemm_hmma<<<gemmBlocks, 256>>>(aggh, w1h, b1,
                                     nullptr, (unsigned*)t1h, stats,
                                     nullptr, nullptr, nullptr, N, 0);
    // gemm2: in = t1h with fp16 BN1+ReLU, out = agg (fp32), stats2
    k_gemm_hmma<<<gemmBlocks, 256>>>(t1h, w2h, b2,
                                     agg, nullptr, stats + 128,
                                     stats, g1, beta1, N, 1);

    k_final<<<(N * 16 + 255) / 256, 256>>>(x, agg, stats + 128, gh, betah, out, N);
}